// round 2
// baseline (speedup 1.0000x reference)
#include <cuda_runtime.h>
#include <math.h>

#define BB   2
#define DD   2048
#define HH   16
#define DHD  128
#define TT   1280
#define LL   2048
#define LIP  512
#define MM   2560      // LL + LIP
#define TWOD 4096

// ------------------------- device scratch -------------------------
__device__ float g_emb[BB * TWOD];                        // shift|scale per batch
__device__ float g_ipn[BB * LIP * DD];                    // adaLN'd ip hidden states
__device__ float g_ipk[BB * LIP * DD];                    // ip_key  (pre-RMS)
__device__ float g_ipv[BB * LIP * DD];                    // ip_value
__device__ float g_q[(size_t)BB * HH * LL * DHD];         // rms(q) * 1/sqrt(d), (b,h,l,dh)
__device__ float g_k[(size_t)BB * HH * MM * DHD];         // [rms(k); rms(kip)]  (b,h,m,dh)
__device__ float g_v[(size_t)BB * HH * MM * DHD];         // [v; vip]

// ------------------------- kernel 1: emb = silu(t) @ W_ada^T + b -------------------------
__global__ void k_emb(const float* __restrict__ t_emb, const float* __restrict__ W,
                      const float* __restrict__ bias) {
    int gw   = (blockIdx.x * blockDim.x + threadIdx.x) >> 5;   // one warp per output
    int lane = threadIdx.x & 31;
    int b = gw >> 12;            // / 4096
    int j = gw & 4095;
    const float* t = t_emb + b * TT;
    const float* w = W + (size_t)j * TT;
    float acc = 0.f;
    #pragma unroll
    for (int i = lane * 4; i < TT; i += 128) {
        float4 tv = *(const float4*)(t + i);
        float4 wv = *(const float4*)(w + i);
        float sx = tv.x / (1.f + __expf(-tv.x));
        float sy = tv.y / (1.f + __expf(-tv.y));
        float sz = tv.z / (1.f + __expf(-tv.z));
        float sw = tv.w / (1.f + __expf(-tv.w));
        acc += sx * wv.x + sy * wv.y + sz * wv.z + sw * wv.w;
    }
    #pragma unroll
    for (int o = 16; o; o >>= 1) acc += __shfl_xor_sync(0xffffffffu, acc, o);
    if (lane == 0) g_emb[gw] = acc + bias[j];
}

// ------------------------- kernel 2: adaLN on ip_hidden_states -------------------------
__global__ void k_ipnorm(const float* __restrict__ ip) {
    __shared__ float red[64];
    int row = blockIdx.x;            // 0 .. B*LIP-1
    int b = row / LIP;
    const float* x = ip + (size_t)row * DD;
    int i0 = threadIdx.x * 8;        // 256 threads * 8 = 2048 = DD
    float4 v0 = *(const float4*)(x + i0);
    float4 v1 = *(const float4*)(x + i0 + 4);
    float s  = v0.x + v0.y + v0.z + v0.w + v1.x + v1.y + v1.z + v1.w;
    float ss = v0.x*v0.x + v0.y*v0.y + v0.z*v0.z + v0.w*v0.w
             + v1.x*v1.x + v1.y*v1.y + v1.z*v1.z + v1.w*v1.w;
    #pragma unroll
    for (int o = 16; o; o >>= 1) {
        s  += __shfl_xor_sync(0xffffffffu, s,  o);
        ss += __shfl_xor_sync(0xffffffffu, ss, o);
    }
    int w = threadIdx.x >> 5, lane = threadIdx.x & 31;
    if (lane == 0) { red[w] = s; red[32 + w] = ss; }
    __syncthreads();
    float fs = 0.f, fss = 0.f;
    #pragma unroll
    for (int k = 0; k < 8; k++) { fs += red[k]; fss += red[32 + k]; }
    float mu   = fs * (1.f / DD);
    float var  = fss * (1.f / DD) - mu * mu;
    float rstd = rsqrtf(var + 1e-6f);
    const float* shp = g_emb + b * TWOD;        // shift
    const float* scp = shp + DD;                // scale
    float* y = g_ipn + (size_t)row * DD;
    float4 sh0 = *(const float4*)(shp + i0), sh1 = *(const float4*)(shp + i0 + 4);
    float4 sc0 = *(const float4*)(scp + i0), sc1 = *(const float4*)(scp + i0 + 4);
    float4 o0, o1;
    o0.x = (v0.x - mu) * rstd * (1.f + sc0.x) + sh0.x;
    o0.y = (v0.y - mu) * rstd * (1.f + sc0.y) + sh0.y;
    o0.z = (v0.z - mu) * rstd * (1.f + sc0.z) + sh0.z;
    o0.w = (v0.w - mu) * rstd * (1.f + sc0.w) + sh0.w;
    o1.x = (v1.x - mu) * rstd * (1.f + sc1.x) + sh1.x;
    o1.y = (v1.y - mu) * rstd * (1.f + sc1.y) + sh1.y;
    o1.z = (v1.z - mu) * rstd * (1.f + sc1.z) + sh1.z;
    o1.w = (v1.w - mu) * rstd * (1.f + sc1.w) + sh1.w;
    *(float4*)(y + i0)     = o0;
    *(float4*)(y + i0 + 4) = o1;
}

// ------------------------- kernel 3: ip_key / ip_value GEMM -------------------------
// C[m][n] = sum_k A[m][k] * W[n][k]   (both K-major), M=1024, N=2048, K=2048
#define GK  16
#define GST 132
__global__ void k_gemm(const float* __restrict__ Wk, const float* __restrict__ Wv) {
    __shared__ float as[GK * GST];   // [k][m], padded
    __shared__ float bs[GK * GST];   // [k][n]
    const float* A  = g_ipn;
    const float* Bm = blockIdx.z ? Wv : Wk;
    float*       C  = blockIdx.z ? g_ipv : g_ipk;
    int m0 = blockIdx.y * 128, n0 = blockIdx.x * 128;
    int tid = threadIdx.x, tx = tid & 15, ty = tid >> 4;
    float c[8][8] = {};
    for (int k0 = 0; k0 < DD; k0 += GK) {
        #pragma unroll
        for (int it = 0; it < 2; it++) {
            int idx = tid + it * 256;          // 0..511
            int m = idx >> 2, kc = (idx & 3) * 4;
            float4 av = *(const float4*)(A  + (size_t)(m0 + m) * DD + k0 + kc);
            float4 bv = *(const float4*)(Bm + (size_t)(n0 + m) * DD + k0 + kc);
            as[(kc + 0) * GST + m] = av.x; as[(kc + 1) * GST + m] = av.y;
            as[(kc + 2) * GST + m] = av.z; as[(kc + 3) * GST + m] = av.w;
            bs[(kc + 0) * GST + m] = bv.x; bs[(kc + 1) * GST + m] = bv.y;
            bs[(kc + 2) * GST + m] = bv.z; bs[(kc + 3) * GST + m] = bv.w;
        }
        __syncthreads();
        #pragma unroll
        for (int kk = 0; kk < GK; kk++) {
            float a[8], bf[8];
            *(float4*)(a)      = *(const float4*)(as + kk * GST + ty * 8);
            *(float4*)(a + 4)  = *(const float4*)(as + kk * GST + ty * 8 + 4);
            *(float4*)(bf)     = *(const float4*)(bs + kk * GST + tx * 8);
            *(float4*)(bf + 4) = *(const float4*)(bs + kk * GST + tx * 8 + 4);
            #pragma unroll
            for (int i = 0; i < 8; i++)
                #pragma unroll
                for (int j = 0; j < 8; j++)
                    c[i][j] = fmaf(a[i], bf[j], c[i][j]);
        }
        __syncthreads();
    }
    #pragma unroll
    for (int i = 0; i < 8; i++) {
        float* cp = C + (size_t)(m0 + ty * 8 + i) * DD + n0 + tx * 8;
        *(float4*)(cp)     = make_float4(c[i][0], c[i][1], c[i][2], c[i][3]);
        *(float4*)(cp + 4) = make_float4(c[i][4], c[i][5], c[i][6], c[i][7]);
    }
}

// ------------------------- kernel 4: RMS-norm + head split/scatter -------------------------
__global__ void k_scatter(const float* __restrict__ q, const float* __restrict__ k,
                          const float* __restrict__ v,
                          const float* __restrict__ wq, const float* __restrict__ wk,
                          const float* __restrict__ wipk) {
    int gw   = (blockIdx.x * blockDim.x + threadIdx.x) >> 5;  // one warp per 128-elem row
    int lane = threadIdx.x & 31;
    const int NQ  = BB * HH * LL;    // 65536
    const int NIP = BB * HH * LIP;   // 16384
    const float* src; float* dst; const float* wptr = nullptr;
    float scale = 1.f; bool do_rms = false;

    int idx = gw;
    if (idx < NQ) {  // q
        int b = idx / (HH * LL), r = idx % (HH * LL), h = r / LL, l = r % LL;
        src = q + (size_t)(b * LL + l) * DD + h * DHD;
        dst = g_q + (size_t)idx * DHD;
        wptr = wq; do_rms = true; scale = 0.08838834764831845f;  // 1/sqrt(128)
    } else if ((idx -= NQ) < NQ) {  // k
        int b = idx / (HH * LL), r = idx % (HH * LL), h = r / LL, l = r % LL;
        src = k + (size_t)(b * LL + l) * DD + h * DHD;
        dst = g_k + ((size_t)(b * HH + h) * MM + l) * DHD;
        wptr = wk; do_rms = true;
    } else if ((idx -= NQ) < NIP) {  // kip
        int b = idx / (HH * LIP), r = idx % (HH * LIP), h = r / LIP, l = r % LIP;
        src = g_ipk + (size_t)(b * LIP + l) * DD + h * DHD;
        dst = g_k + ((size_t)(b * HH + h) * MM + LL + l) * DHD;
        wptr = wipk; do_rms = true;
    } else if ((idx -= NIP) < NQ) {  // v copy
        int b = idx / (HH * LL), r = idx % (HH * LL), h = r / LL, l = r % LL;
        src = v + (size_t)(b * LL + l) * DD + h * DHD;
        dst = g_v + ((size_t)(b * HH + h) * MM + l) * DHD;
    } else {  // vip copy
        idx -= NQ;
        int b = idx / (HH * LIP), r = idx % (HH * LIP), h = r / LIP, l = r % LIP;
        src = g_ipv + (size_t)(b * LIP + l) * DD + h * DHD;
        dst = g_v + ((size_t)(b * HH + h) * MM + LL + l) * DHD;
    }

    float4 val = *(const float4*)(src + lane * 4);
    if (do_rms) {
        float ss = val.x*val.x + val.y*val.y + val.z*val.z + val.w*val.w;
        #pragma unroll
        for (int o = 16; o; o >>= 1) ss += __shfl_xor_sync(0xffffffffu, ss, o);
        float r = rsqrtf(ss * (1.f / DHD) + 1e-6f) * scale;
        float4 w4 = *(const float4*)(wptr + lane * 4);
        val.x *= r * w4.x; val.y *= r * w4.y; val.z *= r * w4.z; val.w *= r * w4.w;
    }
    *(float4*)(dst + lane * 4) = val;
}

// ------------------------- kernel 5: flash attention (fp32) -------------------------
#define AQ  64
#define AK  64
#define QST 132
#define PST 68
__global__ void k_attn(float* __restrict__ out) {
    extern __shared__ float sm[];
    float* q_s = sm;                    // [64][132]
    float* k_s = q_s + AQ * QST;        // [64][132]
    float* v_s = k_s + AK * QST;        // [64][132]
    float* p_s = v_s + AK * QST;        // [64][68]
    int tid = threadIdx.x, tx = tid & 15, ty = tid >> 4;
    int b = blockIdx.z, h = blockIdx.y, qt = blockIdx.x;
    size_t bh = (size_t)b * HH + h;
    const float* Q = g_q + (bh * LL + (size_t)qt * AQ) * DHD;
    const float* K = g_k + bh * MM * DHD;
    const float* V = g_v + bh * MM * DHD;

    #pragma unroll
    for (int it = 0; it < 8; it++) {
        int idx = tid + it * 256;          // 0..2047
        int r = idx >> 5, c = (idx & 31) * 4;
        *(float4*)(q_s + r * QST + c) = *(const float4*)(Q + r * DHD + c);
    }
    float m[4], lsum[4] = {0.f, 0.f, 0.f, 0.f};
    float o[4][8] = {};
    #pragma unroll
    for (int i = 0; i < 4; i++) m[i] = -1e30f;
    __syncthreads();

    for (int kt = 0; kt < MM; kt += AK) {
        #pragma unroll
        for (int it = 0; it < 8; it++) {
            int idx = tid + it * 256;
            int r = idx >> 5, c = (idx & 31) * 4;
            *(float4*)(k_s + r * QST + c) = *(const float4*)(K + (size_t)(kt + r) * DHD + c);
            *(float4*)(v_s + r * QST + c) = *(const float4*)(V + (size_t)(kt + r) * DHD + c);
        }
        __syncthreads();

        // S = Q @ K^T  (rows: ty+16i, cols: tx+16j)
        float s[4][4] = {};
        #pragma unroll 2
        for (int kk = 0; kk < DHD; kk += 4) {
            float4 a[4], bf[4];
            #pragma unroll
            for (int i = 0; i < 4; i++) a[i]  = *(const float4*)(q_s + (ty + 16 * i) * QST + kk);
            #pragma unroll
            for (int j = 0; j < 4; j++) bf[j] = *(const float4*)(k_s + (tx + 16 * j) * QST + kk);
            #pragma unroll
            for (int i = 0; i < 4; i++)
                #pragma unroll
                for (int j = 0; j < 4; j++) {
                    s[i][j] = fmaf(a[i].x, bf[j].x, s[i][j]);
                    s[i][j] = fmaf(a[i].y, bf[j].y, s[i][j]);
                    s[i][j] = fmaf(a[i].z, bf[j].z, s[i][j]);
                    s[i][j] = fmaf(a[i].w, bf[j].w, s[i][j]);
                }
        }

        // online softmax (row reduce across tx: lanes differ in low 4 bits of lane id)
        #pragma unroll
        for (int i = 0; i < 4; i++) {
            float mx = fmaxf(fmaxf(s[i][0], s[i][1]), fmaxf(s[i][2], s[i][3]));
            #pragma unroll
            for (int ofs = 8; ofs; ofs >>= 1) mx = fmaxf(mx, __shfl_xor_sync(0xffffffffu, mx, ofs));
            float mn = fmaxf(m[i], mx);
            float alpha = __expf(m[i] - mn);
            m[i] = mn;
            float rs = 0.f;
            #pragma unroll
            for (int j = 0; j < 4; j++) { s[i][j] = __expf(s[i][j] - mn); rs += s[i][j]; }
            lsum[i] = lsum[i] * alpha + rs;
            #pragma unroll
            for (int c = 0; c < 8; c++) o[i][c] *= alpha;
        }
        #pragma unroll
        for (int i = 0; i < 4; i++)
            #pragma unroll
            for (int j = 0; j < 4; j++)
                p_s[(ty + 16 * i) * PST + tx + 16 * j] = s[i][j];
        __syncthreads();

        // O += P @ V   (O cols: tx*8 .. tx*8+7)
        #pragma unroll 2
        for (int kp = 0; kp < AK; kp++) {
            float p[4];
            #pragma unroll
            for (int i = 0; i < 4; i++) p[i] = p_s[(ty + 16 * i) * PST + kp];
            float4 v0 = *(const float4*)(v_s + kp * QST + tx * 8);
            float4 v1 = *(const float4*)(v_s + kp * QST + tx * 8 + 4);
            #pragma unroll
            for (int i = 0; i < 4; i++) {
                o[i][0] = fmaf(p[i], v0.x, o[i][0]);
                o[i][1] = fmaf(p[i], v0.y, o[i][1]);
                o[i][2] = fmaf(p[i], v0.z, o[i][2]);
                o[i][3] = fmaf(p[i], v0.w, o[i][3]);
                o[i][4] = fmaf(p[i], v1.x, o[i][4]);
                o[i][5] = fmaf(p[i], v1.y, o[i][5]);
                o[i][6] = fmaf(p[i], v1.z, o[i][6]);
                o[i][7] = fmaf(p[i], v1.w, o[i][7]);
            }
        }
        __syncthreads();
    }

    #pragma unroll
    for (int i = 0; i < 4; i++) {
        float ls = lsum[i];
        #pragma unroll
        for (int ofs = 8; ofs; ofs >>= 1) ls += __shfl_xor_sync(0xffffffffu, ls, ofs);
        float inv = 1.f / ls;
        int l = qt * AQ + ty + 16 * i;
        float* op = out + (size_t)(b * LL + l) * DD + h * DHD + tx * 8;
        *(float4*)(op)     = make_float4(o[i][0]*inv, o[i][1]*inv, o[i][2]*inv, o[i][3]*inv);
        *(float4*)(op + 4) = make_float4(o[i][4]*inv, o[i][5]*inv, o[i][6]*inv, o[i][7]*inv);
    }
}

// ------------------------- launch -------------------------
extern "C" void kernel_launch(void* const* d_in, const int* in_sizes, int n_in,
                              void* d_out, int out_size) {
    const float* ip   = (const float*)d_in[0];
    const float* q    = (const float*)d_in[1];
    const float* k    = (const float*)d_in[2];
    const float* v    = (const float*)d_in[3];
    const float* temb = (const float*)d_in[4];
    const float* Wada = (const float*)d_in[5];
    const float* bada = (const float*)d_in[6];
    const float* Wk   = (const float*)d_in[7];
    const float* Wv   = (const float*)d_in[8];
    const float* wq   = (const float*)d_in[9];
    const float* wk   = (const float*)d_in[10];
    const float* wipk = (const float*)d_in[11];
    float* out = (float*)d_out;

    k_emb<<<(BB * TWOD) / 8, 256>>>(temb, Wada, bada);
    k_ipnorm<<<BB * LIP, 256>>>(ip);
    dim3 gg(DD / 128, (BB * LIP) / 128, 2);
    k_gemm<<<gg, 256>>>(Wk, Wv);
    int totw = BB * HH * (LL * 3 + LIP * 2);     // 229376 warps
    k_scatter<<<totw / 8, 256>>>(q, k, v, wq, wk, wipk);

    int smem = (3 * AQ * QST + AK * PST) * sizeof(float);   // 118784 B
    cudaFuncSetAttribute(k_attn, cudaFuncAttributeMaxDynamicSharedMemorySize, smem);
    dim3 ga(LL / AQ, HH, BB);
    k_attn<<<ga, 256, smem>>>(out);
}

// round 3
// speedup vs baseline: 3.5297x; 3.5297x over previous
#include <cuda_runtime.h>
#include <math.h>

#define BB   2
#define DD   2048
#define HH   16
#define DHD  128
#define TT   1280
#define LL   2048
#define LIP  512
#define MM   2560      // LL + LIP
#define TWOD 4096

// ------------------------- device scratch -------------------------
__device__ float g_emb[BB * TWOD];
__device__ float g_ipn[BB * LIP * DD];                    // adaLN'd ip states (tf32-rounded)
__device__ float g_ipk[BB * LIP * DD];
__device__ float g_ipv[BB * LIP * DD];
__device__ float g_wk[DD * DD];                           // tf32-rounded weights
__device__ float g_wv[DD * DD];
__device__ float g_q[(size_t)BB * HH * LL * DHD];         // rms(q)/sqrt(d), tf32 (b,h,l,dh)
__device__ float g_k[(size_t)BB * HH * MM * DHD];         // [rms(k); rms(kip)], tf32
__device__ float g_v[(size_t)BB * HH * MM * DHD];         // [v; vip], tf32

// ------------------------- helpers -------------------------
__device__ __forceinline__ float tf32r(float x) {
    unsigned u; asm("cvt.rna.tf32.f32 %0, %1;" : "=r"(u) : "f"(x));
    return __uint_as_float(u);
}
__device__ __forceinline__ unsigned tf32u(float x) {
    unsigned u; asm("cvt.rna.tf32.f32 %0, %1;" : "=r"(u) : "f"(x));
    return u;
}
__device__ __forceinline__ void mma8(float* d, const unsigned* a, unsigned b0, unsigned b1) {
    asm volatile(
        "mma.sync.aligned.m16n8k8.row.col.f32.tf32.tf32.f32 "
        "{%0,%1,%2,%3},{%4,%5,%6,%7},{%8,%9},{%0,%1,%2,%3};"
        : "+f"(d[0]), "+f"(d[1]), "+f"(d[2]), "+f"(d[3])
        : "r"(a[0]), "r"(a[1]), "r"(a[2]), "r"(a[3]), "r"(b0), "r"(b1));
}
__device__ __forceinline__ void cp16(float* s, const float* g) {
    unsigned a = (unsigned)__cvta_generic_to_shared(s);
    asm volatile("cp.async.cg.shared.global [%0], [%1], 16;" :: "r"(a), "l"(g));
}
#define CPCOMMIT asm volatile("cp.async.commit_group;")
#define CPWAIT(N) asm volatile("cp.async.wait_group %0;" :: "n"(N))

// ------------------------- kernel 0: round weights to tf32 -------------------------
__global__ void k_round(const float* __restrict__ Wk, const float* __restrict__ Wv) {
    int i = blockIdx.x * blockDim.x + threadIdx.x;      // 1M float4s
    float4 a = *(const float4*)(Wk + (size_t)i * 4);
    float4 b = *(const float4*)(Wv + (size_t)i * 4);
    a.x = tf32r(a.x); a.y = tf32r(a.y); a.z = tf32r(a.z); a.w = tf32r(a.w);
    b.x = tf32r(b.x); b.y = tf32r(b.y); b.z = tf32r(b.z); b.w = tf32r(b.w);
    *(float4*)(g_wk + (size_t)i * 4) = a;
    *(float4*)(g_wv + (size_t)i * 4) = b;
}

// ------------------------- kernel 1: emb = silu(t) @ W_ada^T + b -------------------------
__global__ void k_emb(const float* __restrict__ t_emb, const float* __restrict__ W,
                      const float* __restrict__ bias) {
    int gw   = (blockIdx.x * blockDim.x + threadIdx.x) >> 5;
    int lane = threadIdx.x & 31;
    int b = gw >> 12;
    int j = gw & 4095;
    const float* t = t_emb + b * TT;
    const float* w = W + (size_t)j * TT;
    float acc = 0.f;
    #pragma unroll
    for (int i = lane * 4; i < TT; i += 128) {
        float4 tv = *(const float4*)(t + i);
        float4 wv = *(const float4*)(w + i);
        acc += tv.x / (1.f + __expf(-tv.x)) * wv.x;
        acc += tv.y / (1.f + __expf(-tv.y)) * wv.y;
        acc += tv.z / (1.f + __expf(-tv.z)) * wv.z;
        acc += tv.w / (1.f + __expf(-tv.w)) * wv.w;
    }
    #pragma unroll
    for (int o = 16; o; o >>= 1) acc += __shfl_xor_sync(0xffffffffu, acc, o);
    if (lane == 0) g_emb[gw] = acc + bias[j];
}

// ------------------------- kernel 2: adaLN on ip_hidden_states -------------------------
__global__ void k_ipnorm(const float* __restrict__ ip) {
    __shared__ float red[64];
    int row = blockIdx.x;
    int b = row / LIP;
    const float* x = ip + (size_t)row * DD;
    int i0 = threadIdx.x * 8;
    float4 v0 = *(const float4*)(x + i0);
    float4 v1 = *(const float4*)(x + i0 + 4);
    float s  = v0.x + v0.y + v0.z + v0.w + v1.x + v1.y + v1.z + v1.w;
    float ss = v0.x*v0.x + v0.y*v0.y + v0.z*v0.z + v0.w*v0.w
             + v1.x*v1.x + v1.y*v1.y + v1.z*v1.z + v1.w*v1.w;
    #pragma unroll
    for (int o = 16; o; o >>= 1) {
        s  += __shfl_xor_sync(0xffffffffu, s,  o);
        ss += __shfl_xor_sync(0xffffffffu, ss, o);
    }
    int w = threadIdx.x >> 5, lane = threadIdx.x & 31;
    if (lane == 0) { red[w] = s; red[32 + w] = ss; }
    __syncthreads();
    float fs = 0.f, fss = 0.f;
    #pragma unroll
    for (int k = 0; k < 8; k++) { fs += red[k]; fss += red[32 + k]; }
    float mu   = fs * (1.f / DD);
    float var  = fss * (1.f / DD) - mu * mu;
    float rstd = rsqrtf(var + 1e-6f);
    const float* shp = g_emb + b * TWOD;
    const float* scp = shp + DD;
    float* y = g_ipn + (size_t)row * DD;
    float4 sh0 = *(const float4*)(shp + i0), sh1 = *(const float4*)(shp + i0 + 4);
    float4 sc0 = *(const float4*)(scp + i0), sc1 = *(const float4*)(scp + i0 + 4);
    float4 o0, o1;
    o0.x = tf32r((v0.x - mu) * rstd * (1.f + sc0.x) + sh0.x);
    o0.y = tf32r((v0.y - mu) * rstd * (1.f + sc0.y) + sh0.y);
    o0.z = tf32r((v0.z - mu) * rstd * (1.f + sc0.z) + sh0.z);
    o0.w = tf32r((v0.w - mu) * rstd * (1.f + sc0.w) + sh0.w);
    o1.x = tf32r((v1.x - mu) * rstd * (1.f + sc1.x) + sh1.x);
    o1.y = tf32r((v1.y - mu) * rstd * (1.f + sc1.y) + sh1.y);
    o1.z = tf32r((v1.z - mu) * rstd * (1.f + sc1.z) + sh1.z);
    o1.w = tf32r((v1.w - mu) * rstd * (1.f + sc1.w) + sh1.w);
    *(float4*)(y + i0)     = o0;
    *(float4*)(y + i0 + 4) = o1;
}

// ------------------------- kernel 3: tf32 GEMM  C[m][n] = A[m][:] . W[n][:] -------------------------
// A = g_ipn (1024 x 2048), W = g_wk/g_wv (2048 x 2048), C = g_ipk/g_ipv
#define GAST (32 + 4)           // smem row stride (floats) for a 32-wide k-chunk
__global__ void __launch_bounds__(256, 1) k_gemm() {
    extern __shared__ float sm[];
    float* a_s = sm;                       // [2][128][36]
    float* b_s = sm + 2 * 128 * GAST;      // [2][128][36]
    const float* A  = g_ipn;
    const float* Bw = blockIdx.z ? g_wv : g_wk;
    float*       C  = blockIdx.z ? g_ipv : g_ipk;
    int m0 = blockIdx.y * 128, n0 = blockIdx.x * 128;
    int tid = threadIdx.x, w = tid >> 5, lane = tid & 31;
    int g = lane >> 2, q = lane & 3;
    int wm = (w & 3) * 32, wn = (w >> 2) * 64;
    float c[2][8][4] = {};

    auto issue = [&](int ch) {
        int buf = ch & 1;
        float* ad = a_s + buf * 128 * GAST;
        float* bd = b_s + buf * 128 * GAST;
        #pragma unroll
        for (int i = 0; i < 4; i++) {
            int idx = tid + i * 256;              // 0..1023
            int r = idx >> 3, cc = (idx & 7) * 4;
            cp16(ad + r * GAST + cc, A  + (size_t)(m0 + r) * DD + ch * 32 + cc);
            cp16(bd + r * GAST + cc, Bw + (size_t)(n0 + r) * DD + ch * 32 + cc);
        }
    };
    issue(0); CPCOMMIT;

    #pragma unroll 1
    for (int ch = 0; ch < 64; ch++) {
        if (ch + 1 < 64) { issue(ch + 1); CPCOMMIT; CPWAIT(1); }
        else             { CPWAIT(0); }
        __syncthreads();
        float* ab = a_s + (ch & 1) * 128 * GAST;
        float* bb = b_s + (ch & 1) * 128 * GAST;
        #pragma unroll
        for (int t = 0; t < 4; t++) {
            unsigned af[2][4];
            #pragma unroll
            for (int i = 0; i < 2; i++) {
                int r = wm + 16 * i + g;
                af[i][0] = __float_as_uint(ab[r * GAST + 8 * t + q]);
                af[i][1] = __float_as_uint(ab[(r + 8) * GAST + 8 * t + q]);
                af[i][2] = __float_as_uint(ab[r * GAST + 8 * t + q + 4]);
                af[i][3] = __float_as_uint(ab[(r + 8) * GAST + 8 * t + q + 4]);
            }
            #pragma unroll
            for (int j = 0; j < 8; j++) {
                unsigned b0 = __float_as_uint(bb[(wn + 8 * j + g) * GAST + 8 * t + q]);
                unsigned b1 = __float_as_uint(bb[(wn + 8 * j + g) * GAST + 8 * t + q + 4]);
                mma8(c[0][j], af[0], b0, b1);
                mma8(c[1][j], af[1], b0, b1);
            }
        }
        __syncthreads();
    }
    #pragma unroll
    for (int i = 0; i < 2; i++)
        #pragma unroll
        for (int j = 0; j < 8; j++) {
            int r0 = m0 + wm + 16 * i + g, cc = n0 + wn + 8 * j + 2 * q;
            *(float2*)(C + (size_t)r0 * DD + cc)       = make_float2(c[i][j][0], c[i][j][1]);
            *(float2*)(C + (size_t)(r0 + 8) * DD + cc) = make_float2(c[i][j][2], c[i][j][3]);
        }
}

// ------------------------- kernel 4: RMS-norm + head split/scatter (tf32-rounded) -------------------------
__global__ void k_scatter(const float* __restrict__ q, const float* __restrict__ k,
                          const float* __restrict__ v,
                          const float* __restrict__ wq, const float* __restrict__ wk,
                          const float* __restrict__ wipk) {
    int gw   = (blockIdx.x * blockDim.x + threadIdx.x) >> 5;
    int lane = threadIdx.x & 31;
    const int NQ  = BB * HH * LL;
    const int NIP = BB * HH * LIP;
    const float* src; float* dst; const float* wptr = nullptr;
    float scale = 1.f; bool do_rms = false;

    int idx = gw;
    if (idx < NQ) {
        int b = idx / (HH * LL), r = idx % (HH * LL), h = r / LL, l = r % LL;
        src = q + (size_t)(b * LL + l) * DD + h * DHD;
        dst = g_q + (size_t)idx * DHD;
        wptr = wq; do_rms = true; scale = 0.08838834764831845f;
    } else if ((idx -= NQ) < NQ) {
        int b = idx / (HH * LL), r = idx % (HH * LL), h = r / LL, l = r % LL;
        src = k + (size_t)(b * LL + l) * DD + h * DHD;
        dst = g_k + ((size_t)(b * HH + h) * MM + l) * DHD;
        wptr = wk; do_rms = true;
    } else if ((idx -= NQ) < NIP) {
        int b = idx / (HH * LIP), r = idx % (HH * LIP), h = r / LIP, l = r % LIP;
        src = g_ipk + (size_t)(b * LIP + l) * DD + h * DHD;
        dst = g_k + ((size_t)(b * HH + h) * MM + LL + l) * DHD;
        wptr = wipk; do_rms = true;
    } else if ((idx -= NIP) < NQ) {
        int b = idx / (HH * LL), r = idx % (HH * LL), h = r / LL, l = r % LL;
        src = v + (size_t)(b * LL + l) * DD + h * DHD;
        dst = g_v + ((size_t)(b * HH + h) * MM + l) * DHD;
    } else {
        idx -= NQ;
        int b = idx / (HH * LIP), r = idx % (HH * LIP), h = r / LIP, l = r % LIP;
        src = g_ipv + (size_t)(b * LIP + l) * DD + h * DHD;
        dst = g_v + ((size_t)(b * HH + h) * MM + LL + l) * DHD;
    }

    float4 val = *(const float4*)(src + lane * 4);
    if (do_rms) {
        float ss = val.x*val.x + val.y*val.y + val.z*val.z + val.w*val.w;
        #pragma unroll
        for (int o = 16; o; o >>= 1) ss += __shfl_xor_sync(0xffffffffu, ss, o);
        float r = rsqrtf(ss * (1.f / DHD) + 1e-6f) * scale;
        float4 w4 = *(const float4*)(wptr + lane * 4);
        val.x *= r * w4.x; val.y *= r * w4.y; val.z *= r * w4.z; val.w *= r * w4.w;
    }
    val.x = tf32r(val.x); val.y = tf32r(val.y); val.z = tf32r(val.z); val.w = tf32r(val.w);
    *(float4*)(dst + lane * 4) = val;
}

// ------------------------- kernel 5: flash attention (tf32 mma) -------------------------
// CTA: 256 threads (8 warps), Q tile 128 (warp w -> rows 16w..16w+15), KV tile 64.
#define KST 132          // smem row stride (floats) for 128-wide rows
#define NIT (MM / 64)    // 40
__global__ void __launch_bounds__(256, 1) k_attn(float* __restrict__ out) {
    extern __shared__ float sm[];
    float* k_s = sm;                      // [2][64][132]
    float* v_s = sm + 2 * 64 * KST;       // [2][64][132]
    float* q_s = sm + 4 * 64 * KST;       // [128][132]
    int tid = threadIdx.x, w = tid >> 5, lane = tid & 31;
    int g = lane >> 2, q = lane & 3;
    int b = blockIdx.z, h = blockIdx.y, qt = blockIdx.x;
    const float* Q = g_q + ((size_t)(b * HH + h) * LL + (size_t)qt * 128) * DHD;
    const float* K = g_k + (size_t)(b * HH + h) * MM * DHD;
    const float* V = g_v + (size_t)(b * HH + h) * MM * DHD;

    auto loadkv = [&](int it) {
        int buf = it & 1;
        float* kd = k_s + buf * 64 * KST;
        float* vd = v_s + buf * 64 * KST;
        const float* ks = K + (size_t)it * 64 * DHD;
        const float* vs = V + (size_t)it * 64 * DHD;
        #pragma unroll
        for (int i = 0; i < 8; i++) {
            int idx = tid + i * 256;              // 0..2047
            int r = idx >> 5, c = (idx & 31) * 4;
            cp16(kd + r * KST + c, ks + r * DHD + c);
            cp16(vd + r * KST + c, vs + r * DHD + c);
        }
    };
    loadkv(0);
    #pragma unroll
    for (int i = 0; i < 16; i++) {
        int idx = tid + i * 256;
        int r = idx >> 5, c = (idx & 31) * 4;
        cp16(q_s + r * KST + c, Q + r * DHD + c);
    }
    CPCOMMIT;

    unsigned qa[16][4];
    float o[16][4] = {};
    float m0 = -1e30f, m1 = -1e30f, l0 = 0.f, l1 = 0.f;
    int srcA = (lane & ~3) | (q >> 1);
    int srcB = srcA + 2;

    #pragma unroll 1
    for (int it = 0; it < NIT; it++) {
        if (it + 1 < NIT) { loadkv(it + 1); CPCOMMIT; CPWAIT(1); }
        else              { CPWAIT(0); }
        __syncthreads();
        if (it == 0) {
            int r = 16 * w + g;
            #pragma unroll
            for (int t = 0; t < 16; t++) {
                qa[t][0] = __float_as_uint(q_s[r * KST + 8 * t + q]);
                qa[t][1] = __float_as_uint(q_s[(r + 8) * KST + 8 * t + q]);
                qa[t][2] = __float_as_uint(q_s[r * KST + 8 * t + q + 4]);
                qa[t][3] = __float_as_uint(q_s[(r + 8) * KST + 8 * t + q + 4]);
            }
        }
        float* kb = k_s + (it & 1) * 64 * KST;
        float* vb = v_s + (it & 1) * 64 * KST;

        // ---- S = Q @ K^T : 16 k-steps x 8 n-tiles ----
        float s[8][4] = {};
        #pragma unroll
        for (int t = 0; t < 16; t++) {
            #pragma unroll
            for (int j = 0; j < 8; j++) {
                unsigned b0 = __float_as_uint(kb[(8 * j + g) * KST + 8 * t + q]);
                unsigned b1 = __float_as_uint(kb[(8 * j + g) * KST + 8 * t + q + 4]);
                mma8(s[j], qa[t], b0, b1);
            }
        }

        // ---- online softmax (rows g and g+8; reduce across quad lanes) ----
        float mx0 = -1e30f, mx1 = -1e30f;
        #pragma unroll
        for (int j = 0; j < 8; j++) {
            mx0 = fmaxf(mx0, fmaxf(s[j][0], s[j][1]));
            mx1 = fmaxf(mx1, fmaxf(s[j][2], s[j][3]));
        }
        mx0 = fmaxf(mx0, __shfl_xor_sync(0xffffffffu, mx0, 1));
        mx0 = fmaxf(mx0, __shfl_xor_sync(0xffffffffu, mx0, 2));
        mx1 = fmaxf(mx1, __shfl_xor_sync(0xffffffffu, mx1, 1));
        mx1 = fmaxf(mx1, __shfl_xor_sync(0xffffffffu, mx1, 2));
        float nm0 = fmaxf(m0, mx0), nm1 = fmaxf(m1, mx1);
        float al0 = __expf(m0 - nm0), al1 = __expf(m1 - nm1);
        float su0 = 0.f, su1 = 0.f;
        #pragma unroll
        for (int j = 0; j < 8; j++) {
            s[j][0] = __expf(s[j][0] - nm0);
            s[j][1] = __expf(s[j][1] - nm0);
            s[j][2] = __expf(s[j][2] - nm1);
            s[j][3] = __expf(s[j][3] - nm1);
            su0 += s[j][0] + s[j][1];
            su1 += s[j][2] + s[j][3];
        }
        l0 = l0 * al0 + su0; l1 = l1 * al1 + su1;
        m0 = nm0; m1 = nm1;
        #pragma unroll
        for (int nt = 0; nt < 16; nt++) {
            o[nt][0] *= al0; o[nt][1] *= al0;
            o[nt][2] *= al1; o[nt][3] *= al1;
        }

        // ---- O += P @ V : permute S frags to A frags via shuffles ----
        #pragma unroll
        for (int t = 0; t < 8; t++) {
            unsigned p0 = tf32u(s[t][0]), p1 = tf32u(s[t][1]);
            unsigned p2 = tf32u(s[t][2]), p3 = tf32u(s[t][3]);
            unsigned u0 = __shfl_sync(0xffffffffu, p0, srcA);
            unsigned u1 = __shfl_sync(0xffffffffu, p1, srcA);
            unsigned x0 = __shfl_sync(0xffffffffu, p0, srcB);
            unsigned x1 = __shfl_sync(0xffffffffu, p1, srcB);
            unsigned pa[4];
            pa[0] = (q & 1) ? u1 : u0;
            pa[2] = (q & 1) ? x1 : x0;
            u0 = __shfl_sync(0xffffffffu, p2, srcA);
            u1 = __shfl_sync(0xffffffffu, p3, srcA);
            x0 = __shfl_sync(0xffffffffu, p2, srcB);
            x1 = __shfl_sync(0xffffffffu, p3, srcB);
            pa[1] = (q & 1) ? u1 : u0;
            pa[3] = (q & 1) ? x1 : x0;
            #pragma unroll
            for (int nt = 0; nt < 16; nt++) {
                unsigned b0 = __float_as_uint(vb[(8 * t + q) * KST + 8 * nt + g]);
                unsigned b1 = __float_as_uint(vb[(8 * t + q + 4) * KST + 8 * nt + g]);
                mma8(o[nt], pa, b0, b1);
            }
        }
        __syncthreads();
    }

    // ---- epilogue: normalize, stage through smem, coalesced store ----
    l0 += __shfl_xor_sync(0xffffffffu, l0, 1);
    l0 += __shfl_xor_sync(0xffffffffu, l0, 2);
    l1 += __shfl_xor_sync(0xffffffffu, l1, 1);
    l1 += __shfl_xor_sync(0xffffffffu, l1, 2);
    float inv0 = 1.f / l0, inv1 = 1.f / l1;
    int r0 = 16 * w + g;
    #pragma unroll
    for (int nt = 0; nt < 16; nt++) {
        int cc = 8 * nt + 2 * q;
        q_s[r0 * KST + cc]           = o[nt][0] * inv0;
        q_s[r0 * KST + cc + 1]       = o[nt][1] * inv0;
        q_s[(r0 + 8) * KST + cc]     = o[nt][2] * inv1;
        q_s[(r0 + 8) * KST + cc + 1] = o[nt][3] * inv1;
    }
    __syncthreads();
    #pragma unroll
    for (int i = 0; i < 16; i++) {
        int idx = tid + i * 256;
        int r = idx >> 5, c = (idx & 31) * 4;
        *(float4*)(out + ((size_t)(b * LL + qt * 128 + r)) * DD + h * DHD + c) =
            *(const float4*)(q_s + r * KST + c);
    }
}

// ------------------------- launch -------------------------
extern "C" void kernel_launch(void* const* d_in, const int* in_sizes, int n_in,
                              void* d_out, int out_size) {
    const float* ip   = (const float*)d_in[0];
    const float* q    = (const float*)d_in[1];
    const float* k    = (const float*)d_in[2];
    const float* v    = (const float*)d_in[3];
    const float* temb = (const float*)d_in[4];
    const float* Wada = (const float*)d_in[5];
    const float* bada = (const float*)d_in[6];
    const float* Wk   = (const float*)d_in[7];
    const float* Wv   = (const float*)d_in[8];
    const float* wq   = (const float*)d_in[9];
    const float* wk   = (const float*)d_in[10];
    const float* wipk = (const float*)d_in[11];
    float* out = (float*)d_out;

    k_round<<<DD * DD / 4 / 256, 256>>>(Wk, Wv);
    k_emb<<<(BB * TWOD) / 8, 256>>>(temb, Wada, bada);
    k_ipnorm<<<BB * LIP, 256>>>(ip);

    int gemm_smem = 2 * 2 * 128 * GAST * sizeof(float);     // 73728
    cudaFuncSetAttribute(k_gemm, cudaFuncAttributeMaxDynamicSharedMemorySize, gemm_smem);
    dim3 gg(DD / 128, (BB * LIP) / 128, 2);
    k_gemm<<<gg, 256, gemm_smem>>>();

    int totw = BB * HH * (LL * 3 + LIP * 2);
    k_scatter<<<totw / 8, 256>>>(q, k, v, wq, wk, wipk);

    int attn_smem = (4 * 64 * KST + 128 * KST) * sizeof(float);  // 202752
    cudaFuncSetAttribute(k_attn, cudaFuncAttributeMaxDynamicSharedMemorySize, attn_smem);
    dim3 ga(LL / 128, HH, BB);
    k_attn<<<ga, 256, attn_smem>>>(out);
}

// round 5
// speedup vs baseline: 3.6349x; 1.0298x over previous
#include <cuda_runtime.h>
#include <math.h>
#include <stdint.h>

#define BB   2
#define DD   2048
#define HH   16
#define DHD  128
#define TT   1280
#define LL   2048
#define LIP  512
#define MM   2560      // LL + LIP
#define TWOD 4096

// ------------------------- device scratch -------------------------
__device__ float g_emb[BB * TWOD];
__device__ float g_ipn[BB * LIP * DD];                    // adaLN'd ip states (tf32-rounded)
__device__ float g_ipk[BB * LIP * DD];
__device__ float g_ipv[BB * LIP * DD];
__device__ float g_wk[DD * DD];                           // tf32-rounded weights
__device__ float g_wv[DD * DD];
__device__ float g_q[(size_t)BB * HH * LL * DHD];
__device__ float g_k[(size_t)BB * HH * MM * DHD];
__device__ float g_v[(size_t)BB * HH * MM * DHD];

// ------------------------- helpers -------------------------
__device__ __forceinline__ float tf32r(float x) {
    unsigned u; asm("cvt.rna.tf32.f32 %0, %1;" : "=r"(u) : "f"(x));
    return __uint_as_float(u);
}
__device__ __forceinline__ unsigned tf32u(float x) {
    unsigned u; asm("cvt.rna.tf32.f32 %0, %1;" : "=r"(u) : "f"(x));
    return u;
}
__device__ __forceinline__ void mma8(float* d, const unsigned* a, unsigned b0, unsigned b1) {
    asm volatile(
        "mma.sync.aligned.m16n8k8.row.col.f32.tf32.tf32.f32 "
        "{%0,%1,%2,%3},{%4,%5,%6,%7},{%8,%9},{%0,%1,%2,%3};"
        : "+f"(d[0]), "+f"(d[1]), "+f"(d[2]), "+f"(d[3])
        : "r"(a[0]), "r"(a[1]), "r"(a[2]), "r"(a[3]), "r"(b0), "r"(b1));
}
// tf32 fragment loads via ldmatrix: a tf32 m16n8k8 fragment is layout-identical
// to a b16 m16n8k16 fragment (each tf32 = 2 b16 cols).
__device__ __forceinline__ void ldsm4(unsigned* r, uint32_t saddr) {
    asm volatile("ldmatrix.sync.aligned.m8n8.x4.shared.b16 {%0,%1,%2,%3}, [%4];"
        : "=r"(r[0]), "=r"(r[1]), "=r"(r[2]), "=r"(r[3]) : "r"(saddr));
}
__device__ __forceinline__ uint32_t smem_u32(const void* p) {
    return (uint32_t)__cvta_generic_to_shared(p);
}
__device__ __forceinline__ void cp16(void* s, const void* g) {
    unsigned a = (unsigned)__cvta_generic_to_shared(s);
    asm volatile("cp.async.cg.shared.global [%0], [%1], 16;" :: "r"(a), "l"(g));
}
#define CPCOMMIT asm volatile("cp.async.commit_group;")
#define CPWAIT(N) asm volatile("cp.async.wait_group %0;" :: "n"(N))

// ------------------------- kernel 0: round weights to tf32 -------------------------
__global__ void k_round(const float* __restrict__ Wk, const float* __restrict__ Wv) {
    int i = blockIdx.x * blockDim.x + threadIdx.x;
    float4 a = *(const float4*)(Wk + (size_t)i * 4);
    float4 b = *(const float4*)(Wv + (size_t)i * 4);
    a.x = tf32r(a.x); a.y = tf32r(a.y); a.z = tf32r(a.z); a.w = tf32r(a.w);
    b.x = tf32r(b.x); b.y = tf32r(b.y); b.z = tf32r(b.z); b.w = tf32r(b.w);
    *(float4*)(g_wk + (size_t)i * 4) = a;
    *(float4*)(g_wv + (size_t)i * 4) = b;
}

// ------------------------- kernel 1: emb -------------------------
__global__ void k_emb(const float* __restrict__ t_emb, const float* __restrict__ W,
                      const float* __restrict__ bias) {
    int gw   = (blockIdx.x * blockDim.x + threadIdx.x) >> 5;
    int lane = threadIdx.x & 31;
    int b = gw >> 12;
    int j = gw & 4095;
    const float* t = t_emb + b * TT;
    const float* w = W + (size_t)j * TT;
    float acc = 0.f;
    #pragma unroll
    for (int i = lane * 4; i < TT; i += 128) {
        float4 tv = *(const float4*)(t + i);
        float4 wv = *(const float4*)(w + i);
        acc += tv.x / (1.f + __expf(-tv.x)) * wv.x;
        acc += tv.y / (1.f + __expf(-tv.y)) * wv.y;
        acc += tv.z / (1.f + __expf(-tv.z)) * wv.z;
        acc += tv.w / (1.f + __expf(-tv.w)) * wv.w;
    }
    #pragma unroll
    for (int o = 16; o; o >>= 1) acc += __shfl_xor_sync(0xffffffffu, acc, o);
    if (lane == 0) g_emb[gw] = acc + bias[j];
}

// ------------------------- kernel 2: adaLN -------------------------
__global__ void k_ipnorm(const float* __restrict__ ip) {
    __shared__ float red[64];
    int row = blockIdx.x;
    int b = row / LIP;
    const float* x = ip + (size_t)row * DD;
    int i0 = threadIdx.x * 8;
    float4 v0 = *(const float4*)(x + i0);
    float4 v1 = *(const float4*)(x + i0 + 4);
    float s  = v0.x + v0.y + v0.z + v0.w + v1.x + v1.y + v1.z + v1.w;
    float ss = v0.x*v0.x + v0.y*v0.y + v0.z*v0.z + v0.w*v0.w
             + v1.x*v1.x + v1.y*v1.y + v1.z*v1.z + v1.w*v1.w;
    #pragma unroll
    for (int o = 16; o; o >>= 1) {
        s  += __shfl_xor_sync(0xffffffffu, s,  o);
        ss += __shfl_xor_sync(0xffffffffu, ss, o);
    }
    int w = threadIdx.x >> 5, lane = threadIdx.x & 31;
    if (lane == 0) { red[w] = s; red[32 + w] = ss; }
    __syncthreads();
    float fs = 0.f, fss = 0.f;
    #pragma unroll
    for (int k = 0; k < 8; k++) { fs += red[k]; fss += red[32 + k]; }
    float mu   = fs * (1.f / DD);
    float var  = fss * (1.f / DD) - mu * mu;
    float rstd = rsqrtf(var + 1e-6f);
    const float* shp = g_emb + b * TWOD;
    const float* scp = shp + DD;
    float* y = g_ipn + (size_t)row * DD;
    float4 sh0 = *(const float4*)(shp + i0), sh1 = *(const float4*)(shp + i0 + 4);
    float4 sc0 = *(const float4*)(scp + i0), sc1 = *(const float4*)(scp + i0 + 4);
    float4 o0, o1;
    o0.x = tf32r((v0.x - mu) * rstd * (1.f + sc0.x) + sh0.x);
    o0.y = tf32r((v0.y - mu) * rstd * (1.f + sc0.y) + sh0.y);
    o0.z = tf32r((v0.z - mu) * rstd * (1.f + sc0.z) + sh0.z);
    o0.w = tf32r((v0.w - mu) * rstd * (1.f + sc0.w) + sh0.w);
    o1.x = tf32r((v1.x - mu) * rstd * (1.f + sc1.x) + sh1.x);
    o1.y = tf32r((v1.y - mu) * rstd * (1.f + sc1.y) + sh1.y);
    o1.z = tf32r((v1.z - mu) * rstd * (1.f + sc1.z) + sh1.z);
    o1.w = tf32r((v1.w - mu) * rstd * (1.f + sc1.w) + sh1.w);
    *(float4*)(y + i0)     = o0;
    *(float4*)(y + i0 + 4) = o1;
}

// ------------------------- kernel 3: tf32 GEMM (ldmatrix feeds) -------------------------
// C[m][n] = A[m][:] . W[n][:], A=g_ipn (1024x2048), W 2048x2048, K-major.
// smem: [row 0..127][32 k floats], stride GAST (bank group = 4r mod 32, LDSM conflict-free)
#define GAST 36
__global__ void __launch_bounds__(256, 2) k_gemm() {
    extern __shared__ float sm[];
    float* a_s = sm;                       // [2][128][36]
    float* b_s = sm + 2 * 128 * GAST;      // [2][128][36]
    const float* A  = g_ipn;
    const float* Bw = blockIdx.z ? g_wv : g_wk;
    float*       C  = blockIdx.z ? g_ipv : g_ipk;
    int m0 = blockIdx.y * 128, n0 = blockIdx.x * 128;
    int tid = threadIdx.x, w = tid >> 5, lane = tid & 31;
    int g = lane >> 2, q = lane & 3;
    int mi = lane >> 3, r = lane & 7;
    int wm = (w & 3) * 32, wn = (w >> 2) * 64;
    // per-lane ldmatrix offsets (floats)
    uint32_t aoff = ((mi & 1) * 8 + r) * GAST + (mi >> 1) * 4;
    uint32_t boff = r * GAST + (mi >> 1) * 8 + (mi & 1) * 4;
    float c[2][8][4] = {};

    auto issue = [&](int ch) {
        int buf = ch & 1;
        float* ad = a_s + buf * 128 * GAST;
        float* bd = b_s + buf * 128 * GAST;
        #pragma unroll
        for (int i = 0; i < 4; i++) {
            int idx = tid + i * 256;              // 0..1023
            int rr = idx >> 3, cc = (idx & 7) * 4;
            cp16(ad + rr * GAST + cc, A  + (size_t)(m0 + rr) * DD + ch * 32 + cc);
            cp16(bd + rr * GAST + cc, Bw + (size_t)(n0 + rr) * DD + ch * 32 + cc);
        }
    };
    issue(0); CPCOMMIT;

    #pragma unroll 1
    for (int ch = 0; ch < 64; ch++) {
        if (ch + 1 < 64) { issue(ch + 1); CPCOMMIT; CPWAIT(1); }
        else             { CPWAIT(0); }
        __syncthreads();
        uint32_t au = smem_u32(a_s + (ch & 1) * 128 * GAST);
        uint32_t bu = smem_u32(b_s + (ch & 1) * 128 * GAST);
        #pragma unroll
        for (int tp = 0; tp < 2; tp++) {
            unsigned af[2][2][4];       // [t-in-pair][m-tile][frag]
            #pragma unroll
            for (int tm = 0; tm < 2; tm++)
                #pragma unroll
                for (int i = 0; i < 2; i++)
                    ldsm4(af[tm][i], au + 4 * ((wm + 16 * i) * GAST + 8 * (2 * tp + tm) + aoff));
            #pragma unroll
            for (int j = 0; j < 8; j++) {
                unsigned bf[4];
                ldsm4(bf, bu + 4 * ((wn + 8 * j) * GAST + 16 * tp + boff));
                mma8(c[0][j], af[0][0], bf[0], bf[1]);
                mma8(c[1][j], af[0][1], bf[0], bf[1]);
                mma8(c[0][j], af[1][0], bf[2], bf[3]);
                mma8(c[1][j], af[1][1], bf[2], bf[3]);
            }
        }
        __syncthreads();
    }
    #pragma unroll
    for (int i = 0; i < 2; i++)
        #pragma unroll
        for (int j = 0; j < 8; j++) {
            int r0 = m0 + wm + 16 * i + g, cc = n0 + wn + 8 * j + 2 * q;
            *(float2*)(C + (size_t)r0 * DD + cc)       = make_float2(c[i][j][0], c[i][j][1]);
            *(float2*)(C + (size_t)(r0 + 8) * DD + cc) = make_float2(c[i][j][2], c[i][j][3]);
        }
}

// ------------------------- kernel 4: RMS-norm + head split/scatter -------------------------
__global__ void k_scatter(const float* __restrict__ q, const float* __restrict__ k,
                          const float* __restrict__ v,
                          const float* __restrict__ wq, const float* __restrict__ wk,
                          const float* __restrict__ wipk) {
    int gw   = (blockIdx.x * blockDim.x + threadIdx.x) >> 5;
    int lane = threadIdx.x & 31;
    const int NQ  = BB * HH * LL;
    const int NIP = BB * HH * LIP;
    const float* src; float* dst; const float* wptr = nullptr;
    float scale = 1.f; bool do_rms = false;

    int idx = gw;
    if (idx < NQ) {
        int b = idx / (HH * LL), r = idx % (HH * LL), h = r / LL, l = r % LL;
        src = q + (size_t)(b * LL + l) * DD + h * DHD;
        dst = g_q + (size_t)idx * DHD;
        wptr = wq; do_rms = true; scale = 0.08838834764831845f;
    } else if ((idx -= NQ) < NQ) {
        int b = idx / (HH * LL), r = idx % (HH * LL), h = r / LL, l = r % LL;
        src = k + (size_t)(b * LL + l) * DD + h * DHD;
        dst = g_k + ((size_t)(b * HH + h) * MM + l) * DHD;
        wptr = wk; do_rms = true;
    } else if ((idx -= NQ) < NIP) {
        int b = idx / (HH * LIP), r = idx % (HH * LIP), h = r / LIP, l = r % LIP;
        src = g_ipk + (size_t)(b * LIP + l) * DD + h * DHD;
        dst = g_k + ((size_t)(b * HH + h) * MM + LL + l) * DHD;
        wptr = wipk; do_rms = true;
    } else if ((idx -= NIP) < NQ) {
        int b = idx / (HH * LL), r = idx % (HH * LL), h = r / LL, l = r % LL;
        src = v + (size_t)(b * LL + l) * DD + h * DHD;
        dst = g_v + ((size_t)(b * HH + h) * MM + l) * DHD;
    } else {
        idx -= NQ;
        int b = idx / (HH * LIP), r = idx % (HH * LIP), h = r / LIP, l = r % LIP;
        src = g_ipv + (size_t)(b * LIP + l) * DD + h * DHD;
        dst = g_v + ((size_t)(b * HH + h) * MM + LL + l) * DHD;
    }

    float4 val = *(const float4*)(src + lane * 4);
    if (do_rms) {
        float ss = val.x*val.x + val.y*val.y + val.z*val.z + val.w*val.w;
        #pragma unroll
        for (int o = 16; o; o >>= 1) ss += __shfl_xor_sync(0xffffffffu, ss, o);
        float r = rsqrtf(ss * (1.f / DHD) + 1e-6f) * scale;
        float4 w4 = *(const float4*)(wptr + lane * 4);
        val.x *= r * w4.x; val.y *= r * w4.y; val.z *= r * w4.z; val.w *= r * w4.w;
    }
    val.x = tf32r(val.x); val.y = tf32r(val.y); val.z = tf32r(val.z); val.w = tf32r(val.w);
    *(float4*)(dst + lane * 4) = val;
}

// ------------------------- kernel 5: flash attention (tf32 mma + ldmatrix) -------------------------
#define KST 132
#define NIT (MM / 64)
__global__ void __launch_bounds__(256, 1) k_attn(float* __restrict__ out) {
    extern __shared__ float sm[];
    float* k_s = sm;
    float* v_s = sm + 2 * 64 * KST;
    float* q_s = sm + 4 * 64 * KST;
    int tid = threadIdx.x, w = tid >> 5, lane = tid & 31;
    int g = lane >> 2, q = lane & 3;
    int mi = lane >> 3, r = lane & 7;
    int b = blockIdx.z, h = blockIdx.y, qt = blockIdx.x;
    const float* Q = g_q + ((size_t)(b * HH + h) * LL + (size_t)qt * 128) * DHD;
    const float* K = g_k + (size_t)(b * HH + h) * MM * DHD;
    const float* V = g_v + (size_t)(b * HH + h) * MM * DHD;
    // ldmatrix per-lane offset (floats) for B-frags: matrices {t h0, t h1, t+1 h0, t+1 h1}
    uint32_t boff = r * KST + (mi >> 1) * 8 + (mi & 1) * 4;

    auto loadkv = [&](int it) {
        int buf = it & 1;
        float* kd = k_s + buf * 64 * KST;
        float* vd = v_s + buf * 64 * KST;
        const float* ks = K + (size_t)it * 64 * DHD;
        const float* vs = V + (size_t)it * 64 * DHD;
        #pragma unroll
        for (int i = 0; i < 8; i++) {
            int idx = tid + i * 256;
            int rr = idx >> 5, c = (idx & 31) * 4;
            cp16(kd + rr * KST + c, ks + rr * DHD + c);
            cp16(vd + rr * KST + c, vs + rr * DHD + c);
        }
    };
    loadkv(0);
    #pragma unroll
    for (int i = 0; i < 16; i++) {
        int idx = tid + i * 256;
        int rr = idx >> 5, c = (idx & 31) * 4;
        cp16(q_s + rr * KST + c, Q + rr * DHD + c);
    }
    CPCOMMIT;

    unsigned qa[16][4];
    float o[16][4] = {};
    float m0 = -1e30f, m1 = -1e30f, l0 = 0.f, l1 = 0.f;
    int srcA = (lane & ~3) | (q >> 1);
    int srcB = srcA + 2;

    #pragma unroll 1
    for (int it = 0; it < NIT; it++) {
        if (it + 1 < NIT) { loadkv(it + 1); CPCOMMIT; CPWAIT(1); }
        else              { CPWAIT(0); }
        __syncthreads();
        if (it == 0) {
            int rr = 16 * w + g;
            #pragma unroll
            for (int t = 0; t < 16; t++) {
                qa[t][0] = __float_as_uint(q_s[rr * KST + 8 * t + q]);
                qa[t][1] = __float_as_uint(q_s[(rr + 8) * KST + 8 * t + q]);
                qa[t][2] = __float_as_uint(q_s[rr * KST + 8 * t + q + 4]);
                qa[t][3] = __float_as_uint(q_s[(rr + 8) * KST + 8 * t + q + 4]);
            }
        }
        float* vb = v_s + (it & 1) * 64 * KST;
        uint32_t ku = smem_u32(k_s + (it & 1) * 64 * KST);

        // ---- S = Q @ K^T : B-frags via ldmatrix.x4 (t-pair per load) ----
        float s[8][4] = {};
        #pragma unroll
        for (int tp = 0; tp < 8; tp++) {
            #pragma unroll
            for (int j = 0; j < 8; j++) {
                unsigned bf[4];
                ldsm4(bf, ku + 4 * (8 * j * KST + 16 * tp + boff));
                mma8(s[j], qa[2 * tp],     bf[0], bf[1]);
                mma8(s[j], qa[2 * tp + 1], bf[2], bf[3]);
            }
        }

        // ---- online softmax ----
        float mx0 = -1e30f, mx1 = -1e30f;
        #pragma unroll
        for (int j = 0; j < 8; j++) {
            mx0 = fmaxf(mx0, fmaxf(s[j][0], s[j][1]));
            mx1 = fmaxf(mx1, fmaxf(s[j][2], s[j][3]));
        }
        mx0 = fmaxf(mx0, __shfl_xor_sync(0xffffffffu, mx0, 1));
        mx0 = fmaxf(mx0, __shfl_xor_sync(0xffffffffu, mx0, 2));
        mx1 = fmaxf(mx1, __shfl_xor_sync(0xffffffffu, mx1, 1));
        mx1 = fmaxf(mx1, __shfl_xor_sync(0xffffffffu, mx1, 2));
        float nm0 = fmaxf(m0, mx0), nm1 = fmaxf(m1, mx1);
        float al0 = __expf(m0 - nm0), al1 = __expf(m1 - nm1);
        float su0 = 0.f, su1 = 0.f;
        #pragma unroll
        for (int j = 0; j < 8; j++) {
            s[j][0] = __expf(s[j][0] - nm0);
            s[j][1] = __expf(s[j][1] - nm0);
            s[j][2] = __expf(s[j][2] - nm1);
            s[j][3] = __expf(s[j][3] - nm1);
            su0 += s[j][0] + s[j][1];
            su1 += s[j][2] + s[j][3];
        }
        l0 = l0 * al0 + su0; l1 = l1 * al1 + su1;
        m0 = nm0; m1 = nm1;
        #pragma unroll
        for (int nt = 0; nt < 16; nt++) {
            o[nt][0] *= al0; o[nt][1] *= al0;
            o[nt][2] *= al1; o[nt][3] *= al1;
        }

        // ---- O += P @ V : S->A frag permute via shuffles, V scalar LDS ----
        #pragma unroll
        for (int t = 0; t < 8; t++) {
            unsigned p0 = tf32u(s[t][0]), p1 = tf32u(s[t][1]);
            unsigned p2 = tf32u(s[t][2]), p3 = tf32u(s[t][3]);
            unsigned u0 = __shfl_sync(0xffffffffu, p0, srcA);
            unsigned u1 = __shfl_sync(0xffffffffu, p1, srcA);
            unsigned x0 = __shfl_sync(0xffffffffu, p0, srcB);
            unsigned x1 = __shfl_sync(0xffffffffu, p1, srcB);
            unsigned pa[4];
            pa[0] = (q & 1) ? u1 : u0;
            pa[2] = (q & 1) ? x1 : x0;
            u0 = __shfl_sync(0xffffffffu, p2, srcA);
            u1 = __shfl_sync(0xffffffffu, p3, srcA);
            x0 = __shfl_sync(0xffffffffu, p2, srcB);
            x1 = __shfl_sync(0xffffffffu, p3, srcB);
            pa[1] = (q & 1) ? u1 : u0;
            pa[3] = (q & 1) ? x1 : x0;
            #pragma unroll
            for (int nt = 0; nt < 16; nt++) {
                unsigned b0 = __float_as_uint(vb[(8 * t + q) * KST + 8 * nt + g]);
                unsigned b1 = __float_as_uint(vb[(8 * t + q + 4) * KST + 8 * nt + g]);
                mma8(o[nt], pa, b0, b1);
            }
        }
        __syncthreads();
    }

    l0 += __shfl_xor_sync(0xffffffffu, l0, 1);
    l0 += __shfl_xor_sync(0xffffffffu, l0, 2);
    l1 += __shfl_xor_sync(0xffffffffu, l1, 1);
    l1 += __shfl_xor_sync(0xffffffffu, l1, 2);
    float inv0 = 1.f / l0, inv1 = 1.f / l1;
    int r0 = 16 * w + g;
    #pragma unroll
    for (int nt = 0; nt < 16; nt++) {
        int cc = 8 * nt + 2 * q;
        q_s[r0 * KST + cc]           = o[nt][0] * inv0;
        q_s[r0 * KST + cc + 1]       = o[nt][1] * inv0;
        q_s[(r0 + 8) * KST + cc]     = o[nt][2] * inv1;
        q_s[(r0 + 8) * KST + cc + 1] = o[nt][3] * inv1;
    }
    __syncthreads();
    #pragma unroll
    for (int i = 0; i < 16; i++) {
        int idx = tid + i * 256;
        int rr = idx >> 5, c = (idx & 31) * 4;
        *(float4*)(out + ((size_t)(b * LL + qt * 128 + rr)) * DD + h * DHD + c) =
            *(const float4*)(q_s + rr * KST + c);
    }
}

// ------------------------- launch -------------------------
extern "C" void kernel_launch(void* const* d_in, const int* in_sizes, int n_in,
                              void* d_out, int out_size) {
    const float* ip   = (const float*)d_in[0];
    const float* q    = (const float*)d_in[1];
    const float* k    = (const float*)d_in[2];
    const float* v    = (const float*)d_in[3];
    const float* temb = (const float*)d_in[4];
    const float* Wada = (const float*)d_in[5];
    const float* bada = (const float*)d_in[6];
    const float* Wk   = (const float*)d_in[7];
    const float* Wv   = (const float*)d_in[8];
    const float* wq   = (const float*)d_in[9];
    const float* wk   = (const float*)d_in[10];
    const float* wipk = (const float*)d_in[11];
    float* out = (float*)d_out;

    k_round<<<DD * DD / 4 / 256, 256>>>(Wk, Wv);
    k_emb<<<(BB * TWOD) / 8, 256>>>(temb, Wada, bada);
    k_ipnorm<<<BB * LIP, 256>>>(ip);

    int gemm_smem = 2 * 2 * 128 * GAST * sizeof(float);     // 73728
    cudaFuncSetAttribute(k_gemm, cudaFuncAttributeMaxDynamicSharedMemorySize, gemm_smem);
    dim3 gg(DD / 128, (BB * LIP) / 128, 2);
    k_gemm<<<gg, 256, gemm_smem>>>();

    int totw = BB * HH * (LL * 3 + LIP * 2);
    k_scatter<<<totw / 8, 256>>>(q, k, v, wq, wk, wipk);

    int attn_smem = (4 * 64 * KST + 128 * KST) * sizeof(float);   // 202752
    cudaFuncSetAttribute(k_attn, cudaFuncAttributeMaxDynamicSharedMemorySize, attn_smem);
    dim3 ga(LL / 128, HH, BB);
    k_attn<<<ga, 256, attn_smem>>>(out);
}

// round 6
// speedup vs baseline: 4.4583x; 1.2265x over previous
#include <cuda_runtime.h>
#include <cuda_fp16.h>
#include <math.h>
#include <stdint.h>

#define BB   2
#define DD   2048
#define HH   16
#define DHD  128
#define TT   1280
#define LL   2048
#define LIP  512
#define MM   2560      // LL + LIP
#define TWOD 4096

// ------------------------- device scratch -------------------------
__device__ float g_emb[BB * TWOD];
__device__ float g_ipn[BB * LIP * DD];                    // adaLN'd ip states (tf32-rounded)
__device__ float g_ipk[BB * LIP * DD];
__device__ float g_ipv[BB * LIP * DD];
__device__ float g_wk[DD * DD];                           // tf32-rounded weights
__device__ float g_wv[DD * DD];
__device__ float g_q[(size_t)BB * HH * LL * DHD];
__device__ float g_k[(size_t)BB * HH * MM * DHD];
__device__ __half g_v[(size_t)BB * HH * MM * DHD];        // fp16 V

// ------------------------- helpers -------------------------
__device__ __forceinline__ float tf32r(float x) {
    unsigned u; asm("cvt.rna.tf32.f32 %0, %1;" : "=r"(u) : "f"(x));
    return __uint_as_float(u);
}
__device__ __forceinline__ void mma8(float* d, const unsigned* a, unsigned b0, unsigned b1) {
    asm volatile(
        "mma.sync.aligned.m16n8k8.row.col.f32.tf32.tf32.f32 "
        "{%0,%1,%2,%3},{%4,%5,%6,%7},{%8,%9},{%0,%1,%2,%3};"
        : "+f"(d[0]), "+f"(d[1]), "+f"(d[2]), "+f"(d[3])
        : "r"(a[0]), "r"(a[1]), "r"(a[2]), "r"(a[3]), "r"(b0), "r"(b1));
}
__device__ __forceinline__ void mma16f16(float* d, const unsigned* a, unsigned b0, unsigned b1) {
    asm volatile(
        "mma.sync.aligned.m16n8k16.row.col.f32.f16.f16.f32 "
        "{%0,%1,%2,%3},{%4,%5,%6,%7},{%8,%9},{%0,%1,%2,%3};"
        : "+f"(d[0]), "+f"(d[1]), "+f"(d[2]), "+f"(d[3])
        : "r"(a[0]), "r"(a[1]), "r"(a[2]), "r"(a[3]), "r"(b0), "r"(b1));
}
__device__ __forceinline__ void ldsm4(unsigned* r, uint32_t saddr) {
    asm volatile("ldmatrix.sync.aligned.m8n8.x4.shared.b16 {%0,%1,%2,%3}, [%4];"
        : "=r"(r[0]), "=r"(r[1]), "=r"(r[2]), "=r"(r[3]) : "r"(saddr));
}
__device__ __forceinline__ void ldsm4t(unsigned* r, uint32_t saddr) {
    asm volatile("ldmatrix.sync.aligned.m8n8.x4.trans.shared.b16 {%0,%1,%2,%3}, [%4];"
        : "=r"(r[0]), "=r"(r[1]), "=r"(r[2]), "=r"(r[3]) : "r"(saddr));
}
__device__ __forceinline__ uint32_t smem_u32(const void* p) {
    return (uint32_t)__cvta_generic_to_shared(p);
}
__device__ __forceinline__ void cp16(void* s, const void* g) {
    unsigned a = (unsigned)__cvta_generic_to_shared(s);
    asm volatile("cp.async.cg.shared.global [%0], [%1], 16;" :: "r"(a), "l"(g));
}
#define CPCOMMIT asm volatile("cp.async.commit_group;")
#define CPWAIT(N) asm volatile("cp.async.wait_group %0;" :: "n"(N))

// ------------------------- kernel 0: round weights to tf32 -------------------------
__global__ void k_round(const float* __restrict__ Wk, const float* __restrict__ Wv) {
    int i = blockIdx.x * blockDim.x + threadIdx.x;
    float4 a = *(const float4*)(Wk + (size_t)i * 4);
    float4 b = *(const float4*)(Wv + (size_t)i * 4);
    a.x = tf32r(a.x); a.y = tf32r(a.y); a.z = tf32r(a.z); a.w = tf32r(a.w);
    b.x = tf32r(b.x); b.y = tf32r(b.y); b.z = tf32r(b.z); b.w = tf32r(b.w);
    *(float4*)(g_wk + (size_t)i * 4) = a;
    *(float4*)(g_wv + (size_t)i * 4) = b;
}

// ------------------------- kernel 1: emb -------------------------
__global__ void k_emb(const float* __restrict__ t_emb, const float* __restrict__ W,
                      const float* __restrict__ bias) {
    int gw   = (blockIdx.x * blockDim.x + threadIdx.x) >> 5;
    int lane = threadIdx.x & 31;
    int b = gw >> 12;
    int j = gw & 4095;
    const float* t = t_emb + b * TT;
    const float* w = W + (size_t)j * TT;
    float acc = 0.f;
    #pragma unroll
    for (int i = lane * 4; i < TT; i += 128) {
        float4 tv = *(const float4*)(t + i);
        float4 wv = *(const float4*)(w + i);
        acc += tv.x / (1.f + __expf(-tv.x)) * wv.x;
        acc += tv.y / (1.f + __expf(-tv.y)) * wv.y;
        acc += tv.z / (1.f + __expf(-tv.z)) * wv.z;
        acc += tv.w / (1.f + __expf(-tv.w)) * wv.w;
    }
    #pragma unroll
    for (int o = 16; o; o >>= 1) acc += __shfl_xor_sync(0xffffffffu, acc, o);
    if (lane == 0) g_emb[gw] = acc + bias[j];
}

// ------------------------- kernel 2: adaLN -------------------------
__global__ void k_ipnorm(const float* __restrict__ ip) {
    __shared__ float red[64];
    int row = blockIdx.x;
    int b = row / LIP;
    const float* x = ip + (size_t)row * DD;
    int i0 = threadIdx.x * 8;
    float4 v0 = *(const float4*)(x + i0);
    float4 v1 = *(const float4*)(x + i0 + 4);
    float s  = v0.x + v0.y + v0.z + v0.w + v1.x + v1.y + v1.z + v1.w;
    float ss = v0.x*v0.x + v0.y*v0.y + v0.z*v0.z + v0.w*v0.w
             + v1.x*v1.x + v1.y*v1.y + v1.z*v1.z + v1.w*v1.w;
    #pragma unroll
    for (int o = 16; o; o >>= 1) {
        s  += __shfl_xor_sync(0xffffffffu, s,  o);
        ss += __shfl_xor_sync(0xffffffffu, ss, o);
    }
    int w = threadIdx.x >> 5, lane = threadIdx.x & 31;
    if (lane == 0) { red[w] = s; red[32 + w] = ss; }
    __syncthreads();
    float fs = 0.f, fss = 0.f;
    #pragma unroll
    for (int k = 0; k < 8; k++) { fs += red[k]; fss += red[32 + k]; }
    float mu   = fs * (1.f / DD);
    float var  = fss * (1.f / DD) - mu * mu;
    float rstd = rsqrtf(var + 1e-6f);
    const float* shp = g_emb + b * TWOD;
    const float* scp = shp + DD;
    float* y = g_ipn + (size_t)row * DD;
    float4 sh0 = *(const float4*)(shp + i0), sh1 = *(const float4*)(shp + i0 + 4);
    float4 sc0 = *(const float4*)(scp + i0), sc1 = *(const float4*)(scp + i0 + 4);
    float4 o0, o1;
    o0.x = tf32r((v0.x - mu) * rstd * (1.f + sc0.x) + sh0.x);
    o0.y = tf32r((v0.y - mu) * rstd * (1.f + sc0.y) + sh0.y);
    o0.z = tf32r((v0.z - mu) * rstd * (1.f + sc0.z) + sh0.z);
    o0.w = tf32r((v0.w - mu) * rstd * (1.f + sc0.w) + sh0.w);
    o1.x = tf32r((v1.x - mu) * rstd * (1.f + sc1.x) + sh1.x);
    o1.y = tf32r((v1.y - mu) * rstd * (1.f + sc1.y) + sh1.y);
    o1.z = tf32r((v1.z - mu) * rstd * (1.f + sc1.z) + sh1.z);
    o1.w = tf32r((v1.w - mu) * rstd * (1.f + sc1.w) + sh1.w);
    *(float4*)(y + i0)     = o0;
    *(float4*)(y + i0 + 4) = o1;
}

// ------------------------- kernel 3: tf32 GEMM (ldmatrix feeds) -------------------------
#define GAST 36
__global__ void __launch_bounds__(256, 2) k_gemm() {
    extern __shared__ float sm[];
    float* a_s = sm;
    float* b_s = sm + 2 * 128 * GAST;
    const float* A  = g_ipn;
    const float* Bw = blockIdx.z ? g_wv : g_wk;
    float*       C  = blockIdx.z ? g_ipv : g_ipk;
    int m0 = blockIdx.y * 128, n0 = blockIdx.x * 128;
    int tid = threadIdx.x, w = tid >> 5, lane = tid & 31;
    int g = lane >> 2, q = lane & 3;
    int mi = lane >> 3, r = lane & 7;
    int wm = (w & 3) * 32, wn = (w >> 2) * 64;
    uint32_t aoff = ((mi & 1) * 8 + r) * GAST + (mi >> 1) * 4;
    uint32_t boff = r * GAST + (mi >> 1) * 8 + (mi & 1) * 4;
    float c[2][8][4] = {};

    auto issue = [&](int ch) {
        int buf = ch & 1;
        float* ad = a_s + buf * 128 * GAST;
        float* bd = b_s + buf * 128 * GAST;
        #pragma unroll
        for (int i = 0; i < 4; i++) {
            int idx = tid + i * 256;
            int rr = idx >> 3, cc = (idx & 7) * 4;
            cp16(ad + rr * GAST + cc, A  + (size_t)(m0 + rr) * DD + ch * 32 + cc);
            cp16(bd + rr * GAST + cc, Bw + (size_t)(n0 + rr) * DD + ch * 32 + cc);
        }
    };
    issue(0); CPCOMMIT;

    #pragma unroll 1
    for (int ch = 0; ch < 64; ch++) {
        if (ch + 1 < 64) { issue(ch + 1); CPCOMMIT; CPWAIT(1); }
        else             { CPWAIT(0); }
        __syncthreads();
        uint32_t au = smem_u32(a_s + (ch & 1) * 128 * GAST);
        uint32_t bu = smem_u32(b_s + (ch & 1) * 128 * GAST);
        #pragma unroll
        for (int tp = 0; tp < 2; tp++) {
            unsigned af[2][2][4];
            #pragma unroll
            for (int tm = 0; tm < 2; tm++)
                #pragma unroll
                for (int i = 0; i < 2; i++)
                    ldsm4(af[tm][i], au + 4 * ((wm + 16 * i) * GAST + 8 * (2 * tp + tm) + aoff));
            #pragma unroll
            for (int j = 0; j < 8; j++) {
                unsigned bf[4];
                ldsm4(bf, bu + 4 * ((wn + 8 * j) * GAST + 16 * tp + boff));
                mma8(c[0][j], af[0][0], bf[0], bf[1]);
                mma8(c[1][j], af[0][1], bf[0], bf[1]);
                mma8(c[0][j], af[1][0], bf[2], bf[3]);
                mma8(c[1][j], af[1][1], bf[2], bf[3]);
            }
        }
        __syncthreads();
    }
    #pragma unroll
    for (int i = 0; i < 2; i++)
        #pragma unroll
        for (int j = 0; j < 8; j++) {
            int r0 = m0 + wm + 16 * i + g, cc = n0 + wn + 8 * j + 2 * q;
            *(float2*)(C + (size_t)r0 * DD + cc)       = make_float2(c[i][j][0], c[i][j][1]);
            *(float2*)(C + (size_t)(r0 + 8) * DD + cc) = make_float2(c[i][j][2], c[i][j][3]);
        }
}

// ------------------------- kernel 4: RMS-norm + head split/scatter -------------------------
__global__ void k_scatter(const float* __restrict__ q, const float* __restrict__ k,
                          const float* __restrict__ v,
                          const float* __restrict__ wq, const float* __restrict__ wk,
                          const float* __restrict__ wipk) {
    int gw   = (blockIdx.x * blockDim.x + threadIdx.x) >> 5;
    int lane = threadIdx.x & 31;
    const int NQ  = BB * HH * LL;
    const int NIP = BB * HH * LIP;
    const float* src; float* dst = nullptr; __half* hdst = nullptr;
    const float* wptr = nullptr;
    float scale = 1.f; bool do_rms = false;

    int idx = gw;
    if (idx < NQ) {
        int b = idx / (HH * LL), r = idx % (HH * LL), h = r / LL, l = r % LL;
        src = q + (size_t)(b * LL + l) * DD + h * DHD;
        dst = g_q + (size_t)idx * DHD;
        wptr = wq; do_rms = true; scale = 0.08838834764831845f;
    } else if ((idx -= NQ) < NQ) {
        int b = idx / (HH * LL), r = idx % (HH * LL), h = r / LL, l = r % LL;
        src = k + (size_t)(b * LL + l) * DD + h * DHD;
        dst = g_k + ((size_t)(b * HH + h) * MM + l) * DHD;
        wptr = wk; do_rms = true;
    } else if ((idx -= NQ) < NIP) {
        int b = idx / (HH * LIP), r = idx % (HH * LIP), h = r / LIP, l = r % LIP;
        src = g_ipk + (size_t)(b * LIP + l) * DD + h * DHD;
        dst = g_k + ((size_t)(b * HH + h) * MM + LL + l) * DHD;
        wptr = wipk; do_rms = true;
    } else if ((idx -= NIP) < NQ) {
        int b = idx / (HH * LL), r = idx % (HH * LL), h = r / LL, l = r % LL;
        src = v + (size_t)(b * LL + l) * DD + h * DHD;
        hdst = g_v + ((size_t)(b * HH + h) * MM + l) * DHD;
    } else {
        idx -= NQ;
        int b = idx / (HH * LIP), r = idx % (HH * LIP), h = r / LIP, l = r % LIP;
        src = g_ipv + (size_t)(b * LIP + l) * DD + h * DHD;
        hdst = g_v + ((size_t)(b * HH + h) * MM + LL + l) * DHD;
    }

    float4 val = *(const float4*)(src + lane * 4);
    if (do_rms) {
        float ss = val.x*val.x + val.y*val.y + val.z*val.z + val.w*val.w;
        #pragma unroll
        for (int o = 16; o; o >>= 1) ss += __shfl_xor_sync(0xffffffffu, ss, o);
        float r = rsqrtf(ss * (1.f / DHD) + 1e-6f) * scale;
        float4 w4 = *(const float4*)(wptr + lane * 4);
        val.x *= r * w4.x; val.y *= r * w4.y; val.z *= r * w4.z; val.w *= r * w4.w;
    }
    if (hdst) {
        __half2 h0 = __floats2half2_rn(val.x, val.y);
        __half2 h1 = __floats2half2_rn(val.z, val.w);
        *(__half2*)(hdst + lane * 4)     = h0;
        *(__half2*)(hdst + lane * 4 + 2) = h1;
    } else {
        val.x = tf32r(val.x); val.y = tf32r(val.y); val.z = tf32r(val.z); val.w = tf32r(val.w);
        *(float4*)(dst + lane * 4) = val;
    }
}

// ------------------------- kernel 5: flash attention (tf32 QK + fp16 PV) -------------------------
// CTA: 128 threads (4 warps). Q tile 64 rows (warp w -> rows 16w..16w+15), KV tile 64.
// smem: k_s fp32 [2][64][132] (Q staged through it), v_s fp16 [2][64][136]. 100 KB -> 2 CTAs/SM.
#define KST 132
#define VST 136
#define KVT 64
#define NIT (MM / KVT)    // 40
#define KBYTES (2 * KVT * KST * 4)
__global__ void __launch_bounds__(128) k_attn(float* __restrict__ out) {
    extern __shared__ char smc[];
    float*  k_s = (float*)smc;                     // 2*64*132 floats = 67584 B
    __half* v_s = (__half*)(smc + KBYTES);         // 2*64*136 halves = 34816 B
    int tid = threadIdx.x, w = tid >> 5, lane = tid & 31;
    int g = lane >> 2, q = lane & 3;
    int mi = lane >> 3, r = lane & 7;
    int b = blockIdx.z, h = blockIdx.y, qt = blockIdx.x;
    const float*  Q = g_q + ((size_t)(b * HH + h) * LL + (size_t)qt * 64) * DHD;
    const float*  K = g_k + (size_t)(b * HH + h) * MM * DHD;
    const __half* V = g_v + (size_t)(b * HH + h) * MM * DHD;
    // QK B-frag ldmatrix per-lane offset (floats)
    uint32_t boff = r * KST + (mi >> 1) * 8 + (mi & 1) * 4;
    // PV B-frag ldmatrix.trans per-lane offset (halves)
    int krow = ((lane >> 3) & 1) * 8 + (lane & 7);
    int ncol = (lane >> 4) * 8;
    uint32_t voff = krow * VST + ncol;

    // ---- stage Q through k_s, read A-frags, then start KV pipeline ----
    #pragma unroll
    for (int i = 0; i < 16; i++) {
        int idx = tid + i * 128;
        int rr = idx >> 5, c = (idx & 31) * 4;
        cp16(k_s + rr * KST + c, Q + rr * DHD + c);
    }
    CPCOMMIT; CPWAIT(0);
    __syncthreads();
    unsigned qa[16][4];
    {
        int rr = 16 * w + g;
        #pragma unroll
        for (int t = 0; t < 16; t++) {
            qa[t][0] = __float_as_uint(k_s[rr * KST + 8 * t + q]);
            qa[t][1] = __float_as_uint(k_s[(rr + 8) * KST + 8 * t + q]);
            qa[t][2] = __float_as_uint(k_s[rr * KST + 8 * t + q + 4]);
            qa[t][3] = __float_as_uint(k_s[(rr + 8) * KST + 8 * t + q + 4]);
        }
    }
    __syncthreads();

    auto loadkv = [&](int it) {
        int buf = it & 1;
        float*  kd = k_s + buf * KVT * KST;
        __half* vd = v_s + buf * KVT * VST;
        const float*  ks = K + (size_t)it * KVT * DHD;
        const __half* vs = V + (size_t)it * KVT * DHD;
        #pragma unroll
        for (int i = 0; i < 16; i++) {
            int idx = tid + i * 128;
            int rr = idx >> 5, c = (idx & 31) * 4;
            cp16(kd + rr * KST + c, ks + rr * DHD + c);
        }
        #pragma unroll
        for (int i = 0; i < 8; i++) {
            int idx = tid + i * 128;
            int rr = idx >> 4, c = (idx & 15) * 8;
            cp16(vd + rr * VST + c, vs + rr * DHD + c);
        }
        CPCOMMIT;
    };
    loadkv(0); loadkv(1);

    float o[16][4] = {};
    float m0 = -1e30f, m1 = -1e30f, l0 = 0.f, l1 = 0.f;

    #pragma unroll 1
    for (int it = 0; it < NIT; it++) {
        if (it < NIT - 1) CPWAIT(1); else CPWAIT(0);
        __syncthreads();
        uint32_t ku = smem_u32(k_s + (it & 1) * KVT * KST);
        uint32_t vu = smem_u32(v_s + (it & 1) * KVT * VST);

        // ---- S = Q @ K^T (tf32) ----
        float s[8][4] = {};
        #pragma unroll
        for (int tp = 0; tp < 8; tp++) {
            #pragma unroll
            for (int j = 0; j < 8; j++) {
                unsigned bf[4];
                ldsm4(bf, ku + 4 * (8 * j * KST + 16 * tp + boff));
                mma8(s[j], qa[2 * tp],     bf[0], bf[1]);
                mma8(s[j], qa[2 * tp + 1], bf[2], bf[3]);
            }
        }

        // ---- online softmax ----
        float mx0 = -1e30f, mx1 = -1e30f;
        #pragma unroll
        for (int j = 0; j < 8; j++) {
            mx0 = fmaxf(mx0, fmaxf(s[j][0], s[j][1]));
            mx1 = fmaxf(mx1, fmaxf(s[j][2], s[j][3]));
        }
        mx0 = fmaxf(mx0, __shfl_xor_sync(0xffffffffu, mx0, 1));
        mx0 = fmaxf(mx0, __shfl_xor_sync(0xffffffffu, mx0, 2));
        mx1 = fmaxf(mx1, __shfl_xor_sync(0xffffffffu, mx1, 1));
        mx1 = fmaxf(mx1, __shfl_xor_sync(0xffffffffu, mx1, 2));
        float nm0 = fmaxf(m0, mx0), nm1 = fmaxf(m1, mx1);
        float al0 = __expf(m0 - nm0), al1 = __expf(m1 - nm1);
        float su0 = 0.f, su1 = 0.f;
        #pragma unroll
        for (int j = 0; j < 8; j++) {
            s[j][0] = __expf(s[j][0] - nm0);
            s[j][1] = __expf(s[j][1] - nm0);
            s[j][2] = __expf(s[j][2] - nm1);
            s[j][3] = __expf(s[j][3] - nm1);
            su0 += s[j][0] + s[j][1];
            su1 += s[j][2] + s[j][3];
        }
        l0 = l0 * al0 + su0; l1 = l1 * al1 + su1;
        m0 = nm0; m1 = nm1;
        #pragma unroll
        for (int nt = 0; nt < 16; nt++) {
            o[nt][0] *= al0; o[nt][1] *= al0;
            o[nt][2] *= al1; o[nt][3] *= al1;
        }

        // ---- O += P @ V (fp16): S accumulator frag IS the fp16 A frag ----
        #pragma unroll
        for (int u = 0; u < 4; u++) {
            __half2 h0 = __floats2half2_rn(s[2*u][0],   s[2*u][1]);
            __half2 h1 = __floats2half2_rn(s[2*u][2],   s[2*u][3]);
            __half2 h2 = __floats2half2_rn(s[2*u+1][0], s[2*u+1][1]);
            __half2 h3 = __floats2half2_rn(s[2*u+1][2], s[2*u+1][3]);
            unsigned pa[4] = { *(unsigned*)&h0, *(unsigned*)&h1,
                               *(unsigned*)&h2, *(unsigned*)&h3 };
            #pragma unroll
            for (int nt2 = 0; nt2 < 8; nt2++) {
                unsigned bf[4];
                ldsm4t(bf, vu + 2 * (16 * u * VST + 16 * nt2 + voff));
                mma16f16(o[2 * nt2],     pa, bf[0], bf[1]);
                mma16f16(o[2 * nt2 + 1], pa, bf[2], bf[3]);
            }
        }
        __syncthreads();
        if (it + 2 < NIT) loadkv(it + 2);
    }

    // ---- epilogue: normalize, stage through k_s, coalesced store ----
    l0 += __shfl_xor_sync(0xffffffffu, l0, 1);
    l0 += __shfl_xor_sync(0xffffffffu, l0, 2);
    l1 += __shfl_xor_sync(0xffffffffu, l1, 1);
    l1 += __shfl_xor_sync(0xffffffffu, l1, 2);
    float inv0 = 1.f / l0, inv1 = 1.f / l1;
    int r0 = 16 * w + g;
    #pragma unroll
    for (int nt = 0; nt < 16; nt++) {
        int cc = 8 * nt + 2 * q;
        k_s[r0 * KST + cc]           = o[nt][0] * inv0;
        k_s[r0 * KST + cc + 1]       = o[nt][1] * inv0;
        k_s[(r0 + 8) * KST + cc]     = o[nt][2] * inv1;
        k_s[(r0 + 8) * KST + cc + 1] = o[nt][3] * inv1;
    }
    __syncthreads();
    #pragma unroll
    for (int i = 0; i < 16; i++) {
        int idx = tid + i * 128;
        int rr = idx >> 5, c = (idx & 31) * 4;
        *(float4*)(out + ((size_t)(b * LL + qt * 64 + rr)) * DD + h * DHD + c) =
            *(const float4*)(k_s + rr * KST + c);
    }
}

// ------------------------- launch -------------------------
extern "C" void kernel_launch(void* const* d_in, const int* in_sizes, int n_in,
                              void* d_out, int out_size) {
    const float* ip   = (const float*)d_in[0];
    const float* q    = (const float*)d_in[1];
    const float* k    = (const float*)d_in[2];
    const float* v    = (const float*)d_in[3];
    const float* temb = (const float*)d_in[4];
    const float* Wada = (const float*)d_in[5];
    const float* bada = (const float*)d_in[6];
    const float* Wk   = (const float*)d_in[7];
    const float* Wv   = (const float*)d_in[8];
    const float* wq   = (const float*)d_in[9];
    const float* wk   = (const float*)d_in[10];
    const float* wipk = (const float*)d_in[11];
    float* out = (float*)d_out;

    k_round<<<DD * DD / 4 / 256, 256>>>(Wk, Wv);
    k_emb<<<(BB * TWOD) / 8, 256>>>(temb, Wada, bada);
    k_ipnorm<<<BB * LIP, 256>>>(ip);

    int gemm_smem = 2 * 2 * 128 * GAST * sizeof(float);     // 73728
    cudaFuncSetAttribute(k_gemm, cudaFuncAttributeMaxDynamicSharedMemorySize, gemm_smem);
    dim3 gg(DD / 128, (BB * LIP) / 128, 2);
    k_gemm<<<gg, 256, gemm_smem>>>();

    int totw = BB * HH * (LL * 3 + LIP * 2);
    k_scatter<<<totw / 8, 256>>>(q, k, v, wq, wk, wipk);

    int attn_smem = KBYTES + 2 * KVT * VST * 2;             // 67584 + 34816 = 102400
    cudaFuncSetAttribute(k_attn, cudaFuncAttributeMaxDynamicSharedMemorySize, attn_smem);
    dim3 ga(LL / 64, HH, BB);
    k_attn<<<ga, 128, attn_smem>>>(out);
}

// round 8
// speedup vs baseline: 8.3564x; 1.8744x over previous
#include <cuda_runtime.h>
#include <cuda_fp16.h>
#include <math.h>
#include <stdint.h>

#define BB   2
#define DD   2048
#define HH   16
#define DHD  128
#define TT   1280
#define LL   2048
#define LIP  512
#define MM   2560      // LL + LIP
#define TWOD 4096

// ------------------------- device scratch -------------------------
__device__ float  g_emb[BB * TWOD];
__device__ __half g_ipn[BB * LIP * DD];                   // adaLN'd ip states (fp16)
__device__ float  g_ipk[BB * LIP * DD];                   // GEMM outputs (fp32)
__device__ float  g_ipv[BB * LIP * DD];
__device__ __half g_wk[DD * DD];                          // fp16 weights
__device__ __half g_wv[DD * DD];
__device__ __half g_q[(size_t)BB * HH * LL * DHD];        // fp16 q (rms * 1/sqrt(d))
__device__ __half g_k[(size_t)BB * HH * MM * DHD];        // fp16 [rms(k); rms(kip)]
__device__ __half g_v[(size_t)BB * HH * MM * DHD];        // fp16 [v; vip]

// ------------------------- helpers -------------------------
__device__ __forceinline__ void mma16f16(float* d, const unsigned* a, unsigned b0, unsigned b1) {
    asm volatile(
        "mma.sync.aligned.m16n8k16.row.col.f32.f16.f16.f32 "
        "{%0,%1,%2,%3},{%4,%5,%6,%7},{%8,%9},{%0,%1,%2,%3};"
        : "+f"(d[0]), "+f"(d[1]), "+f"(d[2]), "+f"(d[3])
        : "r"(a[0]), "r"(a[1]), "r"(a[2]), "r"(a[3]), "r"(b0), "r"(b1));
}
__device__ __forceinline__ void ldsm4(unsigned* r, uint32_t saddr) {
    asm volatile("ldmatrix.sync.aligned.m8n8.x4.shared.b16 {%0,%1,%2,%3}, [%4];"
        : "=r"(r[0]), "=r"(r[1]), "=r"(r[2]), "=r"(r[3]) : "r"(saddr));
}
__device__ __forceinline__ void ldsm4t(unsigned* r, uint32_t saddr) {
    asm volatile("ldmatrix.sync.aligned.m8n8.x4.trans.shared.b16 {%0,%1,%2,%3}, [%4];"
        : "=r"(r[0]), "=r"(r[1]), "=r"(r[2]), "=r"(r[3]) : "r"(saddr));
}
__device__ __forceinline__ uint32_t smem_u32(const void* p) {
    return (uint32_t)__cvta_generic_to_shared(p);
}
__device__ __forceinline__ void cp16(void* s, const void* g) {
    unsigned a = (unsigned)__cvta_generic_to_shared(s);
    asm volatile("cp.async.cg.shared.global [%0], [%1], 16;" :: "r"(a), "l"(g));
}
#define CPCOMMIT asm volatile("cp.async.commit_group;")
#define CPWAIT(N) asm volatile("cp.async.wait_group %0;" :: "n"(N))

// ------------------------- kernel 0: weights -> fp16 -------------------------
__global__ void k_round(const float* __restrict__ Wk, const float* __restrict__ Wv) {
    int i = blockIdx.x * blockDim.x + threadIdx.x;      // 8 floats per thread
    float4 a0 = *(const float4*)(Wk + (size_t)i * 8);
    float4 a1 = *(const float4*)(Wk + (size_t)i * 8 + 4);
    float4 b0 = *(const float4*)(Wv + (size_t)i * 8);
    float4 b1 = *(const float4*)(Wv + (size_t)i * 8 + 4);
    __half2 ha[4] = { __floats2half2_rn(a0.x, a0.y), __floats2half2_rn(a0.z, a0.w),
                      __floats2half2_rn(a1.x, a1.y), __floats2half2_rn(a1.z, a1.w) };
    __half2 hb[4] = { __floats2half2_rn(b0.x, b0.y), __floats2half2_rn(b0.z, b0.w),
                      __floats2half2_rn(b1.x, b1.y), __floats2half2_rn(b1.z, b1.w) };
    *(uint4*)(g_wk + (size_t)i * 8) = *(uint4*)ha;
    *(uint4*)(g_wv + (size_t)i * 8) = *(uint4*)hb;
}

// ------------------------- kernel 1: emb -------------------------
__global__ void k_emb(const float* __restrict__ t_emb, const float* __restrict__ W,
                      const float* __restrict__ bias) {
    int gw   = (blockIdx.x * blockDim.x + threadIdx.x) >> 5;
    int lane = threadIdx.x & 31;
    int b = gw >> 12;
    int j = gw & 4095;
    const float* t = t_emb + b * TT;
    const float* w = W + (size_t)j * TT;
    float acc = 0.f;
    #pragma unroll
    for (int i = lane * 4; i < TT; i += 128) {
        float4 tv = *(const float4*)(t + i);
        float4 wv = *(const float4*)(w + i);
        acc += tv.x / (1.f + __expf(-tv.x)) * wv.x;
        acc += tv.y / (1.f + __expf(-tv.y)) * wv.y;
        acc += tv.z / (1.f + __expf(-tv.z)) * wv.z;
        acc += tv.w / (1.f + __expf(-tv.w)) * wv.w;
    }
    #pragma unroll
    for (int o = 16; o; o >>= 1) acc += __shfl_xor_sync(0xffffffffu, acc, o);
    if (lane == 0) g_emb[gw] = acc + bias[j];
}

// ------------------------- kernel 2: adaLN -> fp16 -------------------------
__global__ void k_ipnorm(const float* __restrict__ ip) {
    __shared__ float red[64];
    int row = blockIdx.x;
    int b = row / LIP;
    const float* x = ip + (size_t)row * DD;
    int i0 = threadIdx.x * 8;
    float4 v0 = *(const float4*)(x + i0);
    float4 v1 = *(const float4*)(x + i0 + 4);
    float s  = v0.x + v0.y + v0.z + v0.w + v1.x + v1.y + v1.z + v1.w;
    float ss = v0.x*v0.x + v0.y*v0.y + v0.z*v0.z + v0.w*v0.w
             + v1.x*v1.x + v1.y*v1.y + v1.z*v1.z + v1.w*v1.w;
    #pragma unroll
    for (int o = 16; o; o >>= 1) {
        s  += __shfl_xor_sync(0xffffffffu, s,  o);
        ss += __shfl_xor_sync(0xffffffffu, ss, o);
    }
    int w = threadIdx.x >> 5, lane = threadIdx.x & 31;
    if (lane == 0) { red[w] = s; red[32 + w] = ss; }
    __syncthreads();
    float fs = 0.f, fss = 0.f;
    #pragma unroll
    for (int k = 0; k < 8; k++) { fs += red[k]; fss += red[32 + k]; }
    float mu   = fs * (1.f / DD);
    float var  = fss * (1.f / DD) - mu * mu;
    float rstd = rsqrtf(var + 1e-6f);
    const float* shp = g_emb + b * TWOD;
    const float* scp = shp + DD;
    __half* y = g_ipn + (size_t)row * DD;
    float4 sh0 = *(const float4*)(shp + i0), sh1 = *(const float4*)(shp + i0 + 4);
    float4 sc0 = *(const float4*)(scp + i0), sc1 = *(const float4*)(scp + i0 + 4);
    __half2 h[4];
    h[0] = __floats2half2_rn((v0.x - mu) * rstd * (1.f + sc0.x) + sh0.x,
                             (v0.y - mu) * rstd * (1.f + sc0.y) + sh0.y);
    h[1] = __floats2half2_rn((v0.z - mu) * rstd * (1.f + sc0.z) + sh0.z,
                             (v0.w - mu) * rstd * (1.f + sc0.w) + sh0.w);
    h[2] = __floats2half2_rn((v1.x - mu) * rstd * (1.f + sc1.x) + sh1.x,
                             (v1.y - mu) * rstd * (1.f + sc1.y) + sh1.y);
    h[3] = __floats2half2_rn((v1.z - mu) * rstd * (1.f + sc1.z) + sh1.z,
                             (v1.w - mu) * rstd * (1.f + sc1.w) + sh1.w);
    *(uint4*)(y + i0) = *(uint4*)h;
}

// ------------------------- kernel 3: fp16 GEMM, fp32 accum -------------------------
// C[m][n] = A[m][:] . W[n][:], A=g_ipn (1024x2048 fp16), W (2048x2048 fp16), K-major.
// k-chunk = 32 halves (64 B/row). smem stride 40 halves. 3-stage cp.async.
#define GST 40
#define GNST 3
__global__ void __launch_bounds__(256, 2) k_gemm() {
    extern __shared__ __half hsm[];
    __half* a_s = hsm;                        // [3][128][40]
    __half* b_s = hsm + GNST * 128 * GST;     // [3][128][40]
    const __half* A  = g_ipn;
    const __half* Bw = blockIdx.z ? g_wv : g_wk;
    float*        C  = blockIdx.z ? g_ipv : g_ipk;
    int m0 = blockIdx.y * 128, n0 = blockIdx.x * 128;
    int tid = threadIdx.x, w = tid >> 5, lane = tid & 31;
    int g = lane >> 2, q = lane & 3;
    int mi = lane >> 3, r = lane & 7;
    int wm = (w & 3) * 32, wn = (w >> 2) * 64;
    uint32_t aoff = ((mi & 1) * 8 + r) * GST + (mi >> 1) * 8;     // halves
    uint32_t boff = ((mi >> 1) * 8 + r) * GST + (mi & 1) * 8;     // halves
    float c[2][8][4] = {};

    auto issue = [&](int ch) {
        int st = ch % GNST;
        __half* ad = a_s + st * 128 * GST;
        __half* bd = b_s + st * 128 * GST;
        #pragma unroll
        for (int i = 0; i < 2; i++) {
            int idx = tid + i * 256;              // 0..511 = 128 rows x 4 chunks
            int rr = idx >> 2, cc = (idx & 3) * 8;
            cp16(ad + rr * GST + cc, A  + (size_t)(m0 + rr) * DD + ch * 32 + cc);
            cp16(bd + rr * GST + cc, Bw + (size_t)(n0 + rr) * DD + ch * 32 + cc);
        }
        CPCOMMIT;
    };
    issue(0); issue(1);

    #pragma unroll 1
    for (int ch = 0; ch < 64; ch++) {
        if (ch < 63) CPWAIT(1); else CPWAIT(0);
        __syncthreads();
        int st = ch % GNST;
        uint32_t au = smem_u32(a_s + st * 128 * GST);
        uint32_t bu = smem_u32(b_s + st * 128 * GST);
        #pragma unroll
        for (int ks = 0; ks < 2; ks++) {
            unsigned af[2][4];
            #pragma unroll
            for (int i = 0; i < 2; i++)
                ldsm4(af[i], au + 2 * ((wm + 16 * i) * GST + ks * 16 + aoff));
            #pragma unroll
            for (int j2 = 0; j2 < 4; j2++) {
                unsigned bf[4];
                ldsm4(bf, bu + 2 * ((wn + 16 * j2) * GST + ks * 16 + boff));
                mma16f16(c[0][2 * j2],     af[0], bf[0], bf[1]);
                mma16f16(c[0][2 * j2 + 1], af[0], bf[2], bf[3]);
                mma16f16(c[1][2 * j2],     af[1], bf[0], bf[1]);
                mma16f16(c[1][2 * j2 + 1], af[1], bf[2], bf[3]);
            }
        }
        __syncthreads();
        if (ch + 2 < 64) issue(ch + 2);
    }
    #pragma unroll
    for (int i = 0; i < 2; i++)
        #pragma unroll
        for (int j = 0; j < 8; j++) {
            int r0 = m0 + wm + 16 * i + g, cc = n0 + wn + 8 * j + 2 * q;
            *(float2*)(C + (size_t)r0 * DD + cc)       = make_float2(c[i][j][0], c[i][j][1]);
            *(float2*)(C + (size_t)(r0 + 8) * DD + cc) = make_float2(c[i][j][2], c[i][j][3]);
        }
}

// ------------------------- kernel 4: RMS-norm + head split/scatter -> fp16 -------------------------
__global__ void k_scatter(const float* __restrict__ q, const float* __restrict__ k,
                          const float* __restrict__ v,
                          const float* __restrict__ wq, const float* __restrict__ wk,
                          const float* __restrict__ wipk) {
    int gw   = (blockIdx.x * blockDim.x + threadIdx.x) >> 5;
    int lane = threadIdx.x & 31;
    const int NQ  = BB * HH * LL;
    const int NIP = BB * HH * LIP;
    const float* src; __half* dst; const float* wptr = nullptr;
    float scale = 1.f; bool do_rms = false;

    int idx = gw;
    if (idx < NQ) {
        int b = idx / (HH * LL), r = idx % (HH * LL), h = r / LL, l = r % LL;
        src = q + (size_t)(b * LL + l) * DD + h * DHD;
        dst = g_q + (size_t)idx * DHD;
        wptr = wq; do_rms = true; scale = 0.08838834764831845f;
    } else if ((idx -= NQ) < NQ) {
        int b = idx / (HH * LL), r = idx % (HH * LL), h = r / LL, l = r % LL;
        src = k + (size_t)(b * LL + l) * DD + h * DHD;
        dst = g_k + ((size_t)(b * HH + h) * MM + l) * DHD;
        wptr = wk; do_rms = true;
    } else if ((idx -= NQ) < NIP) {
        int b = idx / (HH * LIP), r = idx % (HH * LIP), h = r / LIP, l = r % LIP;
        src = g_ipk + (size_t)(b * LIP + l) * DD + h * DHD;
        dst = g_k + ((size_t)(b * HH + h) * MM + LL + l) * DHD;
        wptr = wipk; do_rms = true;
    } else if ((idx -= NIP) < NQ) {
        int b = idx / (HH * LL), r = idx % (HH * LL), h = r / LL, l = r % LL;
        src = v + (size_t)(b * LL + l) * DD + h * DHD;
        dst = g_v + ((size_t)(b * HH + h) * MM + l) * DHD;
    } else {
        idx -= NQ;
        int b = idx / (HH * LIP), r = idx % (HH * LIP), h = r / LIP, l = r % LIP;
        src = g_ipv + (size_t)(b * LIP + l) * DD + h * DHD;
        dst = g_v + ((size_t)(b * HH + h) * MM + LL + l) * DHD;
    }

    float4 val = *(const float4*)(src + lane * 4);
    if (do_rms) {
        float ss = val.x*val.x + val.y*val.y + val.z*val.z + val.w*val.w;
        #pragma unroll
        for (int o = 16; o; o >>= 1) ss += __shfl_xor_sync(0xffffffffu, ss, o);
        float r = rsqrtf(ss * (1.f / DHD) + 1e-6f) * scale;
        float4 w4 = *(const float4*)(wptr + lane * 4);
        val.x *= r * w4.x; val.y *= r * w4.y; val.z *= r * w4.z; val.w *= r * w4.w;
    }
    __half2 h0 = __floats2half2_rn(val.x, val.y);
    __half2 h1 = __floats2half2_rn(val.z, val.w);
    *(__half2*)(dst + lane * 4)     = h0;
    *(__half2*)(dst + lane * 4 + 2) = h1;
}

// ------------------------- kernel 5: flash attention, all-fp16 mma -------------------------
// CTA: 128 threads (4 warps). Q tile 64 (warp w -> rows 16w..16w+15), KV tile 64.
// smem: k_s fp16 [2][64][136], v_s fp16 [2][64][136]  (Q staged through k_s). 68 KB.
#define VSTK 136
#define KVT 64
#define NIT (MM / KVT)    // 40
#define KB16 (2 * KVT * VSTK * 2)   // one double-buffered fp16 tile: 34816 B
__global__ void __launch_bounds__(128) k_attn(float* __restrict__ out) {
    extern __shared__ char smc[];
    __half* k_s = (__half*)smc;
    __half* v_s = (__half*)(smc + KB16);
    int tid = threadIdx.x, w = tid >> 5, lane = tid & 31;
    int g = lane >> 2, q = lane & 3;
    int mi = lane >> 3, r = lane & 7;
    int b = blockIdx.z, h = blockIdx.y, qt = blockIdx.x;
    const __half* Q = g_q + ((size_t)(b * HH + h) * LL + (size_t)qt * 64) * DHD;
    const __half* K = g_k + (size_t)(b * HH + h) * MM * DHD;
    const __half* V = g_v + (size_t)(b * HH + h) * MM * DHD;
    // fp16 fragment lane offsets (halves)
    uint32_t aoff = ((mi & 1) * 8 + r) * VSTK + (mi >> 1) * 8;    // A-frag (Q)
    uint32_t boff = ((mi >> 1) * 8 + r) * VSTK + (mi & 1) * 8;    // B-frag (K, k-major)
    int krow = ((lane >> 3) & 1) * 8 + (lane & 7);                // B-frag (V, trans)
    int ncol = (lane >> 4) * 8;
    uint32_t voff = krow * VSTK + ncol;

    // ---- stage Q through k_s (64 rows x 128 halves = 1024 x 16B), read A-frags ----
    #pragma unroll
    for (int i = 0; i < 8; i++) {
        int idx = tid + i * 128;                  // 0..1023
        int rr = idx >> 4, c = (idx & 15) * 8;    // rr 0..63
        cp16(k_s + rr * VSTK + c, Q + rr * DHD + c);
    }
    CPCOMMIT; CPWAIT(0);
    __syncthreads();
    unsigned qa[8][4];
    {
        uint32_t qu = smem_u32(k_s);
        #pragma unroll
        for (int ks = 0; ks < 8; ks++)
            ldsm4(qa[ks], qu + 2 * (16 * w * VSTK + ks * 16 + aoff));
    }
    __syncthreads();

    auto loadkv = [&](int it) {
        int buf = it & 1;
        __half* kd = k_s + buf * KVT * VSTK;
        __half* vd = v_s + buf * KVT * VSTK;
        const __half* ks = K + (size_t)it * KVT * DHD;
        const __half* vs = V + (size_t)it * KVT * DHD;
        #pragma unroll
        for (int i = 0; i < 8; i++) {
            int idx = tid + i * 128;                  // 0..1023
            int rr = idx >> 4, c = (idx & 15) * 8;    // rr 0..63
            cp16(kd + rr * VSTK + c, ks + rr * DHD + c);
            cp16(vd + rr * VSTK + c, vs + rr * DHD + c);
        }
        CPCOMMIT;
    };
    loadkv(0); loadkv(1);

    float o[16][4] = {};
    float m0 = -1e30f, m1 = -1e30f, l0 = 0.f, l1 = 0.f;

    #pragma unroll 1
    for (int it = 0; it < NIT; it++) {
        if (it < NIT - 1) CPWAIT(1); else CPWAIT(0);
        __syncthreads();
        uint32_t ku = smem_u32(k_s + (it & 1) * KVT * VSTK);
        uint32_t vu = smem_u32(v_s + (it & 1) * KVT * VSTK);

        // ---- S = Q @ K^T (fp16, fp32 accum) ----
        float s[8][4] = {};
        #pragma unroll
        for (int j2 = 0; j2 < 4; j2++) {
            #pragma unroll
            for (int ks = 0; ks < 8; ks++) {
                unsigned bf[4];
                ldsm4(bf, ku + 2 * (16 * j2 * VSTK + ks * 16 + boff));
                mma16f16(s[2 * j2],     qa[ks], bf[0], bf[1]);
                mma16f16(s[2 * j2 + 1], qa[ks], bf[2], bf[3]);
            }
        }

        // ---- online softmax ----
        float mx0 = -1e30f, mx1 = -1e30f;
        #pragma unroll
        for (int j = 0; j < 8; j++) {
            mx0 = fmaxf(mx0, fmaxf(s[j][0], s[j][1]));
            mx1 = fmaxf(mx1, fmaxf(s[j][2], s[j][3]));
        }
        mx0 = fmaxf(mx0, __shfl_xor_sync(0xffffffffu, mx0, 1));
        mx0 = fmaxf(mx0, __shfl_xor_sync(0xffffffffu, mx0, 2));
        mx1 = fmaxf(mx1, __shfl_xor_sync(0xffffffffu, mx1, 1));
        mx1 = fmaxf(mx1, __shfl_xor_sync(0xffffffffu, mx1, 2));
        float nm0 = fmaxf(m0, mx0), nm1 = fmaxf(m1, mx1);
        float al0 = __expf(m0 - nm0), al1 = __expf(m1 - nm1);
        float su0 = 0.f, su1 = 0.f;
        #pragma unroll
        for (int j = 0; j < 8; j++) {
            s[j][0] = __expf(s[j][0] - nm0);
            s[j][1] = __expf(s[j][1] - nm0);
            s[j][2] = __expf(s[j][2] - nm1);
            s[j][3] = __expf(s[j][3] - nm1);
            su0 += s[j][0] + s[j][1];
            su1 += s[j][2] + s[j][3];
        }
        l0 = l0 * al0 + su0; l1 = l1 * al1 + su1;
        m0 = nm0; m1 = nm1;
        #pragma unroll
        for (int nt = 0; nt < 16; nt++) {
            o[nt][0] *= al0; o[nt][1] *= al0;
            o[nt][2] *= al1; o[nt][3] *= al1;
        }

        // ---- O += P @ V (fp16): S accumulator frag IS the fp16 A frag ----
        #pragma unroll
        for (int u = 0; u < 4; u++) {
            __half2 h0 = __floats2half2_rn(s[2*u][0],   s[2*u][1]);
            __half2 h1 = __floats2half2_rn(s[2*u][2],   s[2*u][3]);
            __half2 h2 = __floats2half2_rn(s[2*u+1][0], s[2*u+1][1]);
            __half2 h3 = __floats2half2_rn(s[2*u+1][2], s[2*u+1][3]);
            unsigned pa[4] = { *(unsigned*)&h0, *(unsigned*)&h1,
                               *(unsigned*)&h2, *(unsigned*)&h3 };
            #pragma unroll
            for (int nt2 = 0; nt2 < 8; nt2++) {
                unsigned bf[4];
                ldsm4t(bf, vu + 2 * (16 * u * VSTK + 16 * nt2 + voff));
                mma16f16(o[2 * nt2],     pa, bf[0], bf[1]);
                mma16f16(o[2 * nt2 + 1], pa, bf[2], bf[3]);
            }
        }
        __syncthreads();
        if (it + 2 < NIT) loadkv(it + 2);
    }

    // ---- epilogue: normalize, stage through smem (as float), coalesced store ----
    l0 += __shfl_xor_sync(0xffffffffu, l0, 1);
    l0 += __shfl_xor_sync(0xffffffffu, l0, 2);
    l1 += __shfl_xor_sync(0xffffffffu, l1, 1);
    l1 += __shfl_xor_sync(0xffffffffu, l1, 2);
    float inv0 = 1.f / l0, inv1 = 1.f / l1;
    float* o_s = (float*)smc;                 // reuse 68 KB region, stride 132 floats
    int r0 = 16 * w + g;
    #pragma unroll
    for (int nt = 0; nt < 16; nt++) {
        int cc = 8 * nt + 2 * q;
        o_s[r0 * 132 + cc]           = o[nt][0] * inv0;
        o_s[r0 * 132 + cc + 1]       = o[nt][1] * inv0;
        o_s[(r0 + 8) * 132 + cc]     = o[nt][2] * inv1;
        o_s[(r0 + 8) * 132 + cc + 1] = o[nt][3] * inv1;
    }
    __syncthreads();
    #pragma unroll
    for (int i = 0; i < 16; i++) {
        int idx = tid + i * 128;
        int rr = idx >> 5, c = (idx & 31) * 4;
        *(float4*)(out + ((size_t)(b * LL + qt * 64 + rr)) * DD + h * DHD + c) =
            *(const float4*)(o_s + rr * 132 + c);
    }
}

// ------------------------- launch -------------------------
extern "C" void kernel_launch(void* const* d_in, const int* in_sizes, int n_in,
                              void* d_out, int out_size) {
    const float* ip   = (const float*)d_in[0];
    const float* q    = (const float*)d_in[1];
    const float* k    = (const float*)d_in[2];
    const float* v    = (const float*)d_in[3];
    const float* temb = (const float*)d_in[4];
    const float* Wada = (const float*)d_in[5];
    const float* bada = (const float*)d_in[6];
    const float* Wk   = (const float*)d_in[7];
    const float* Wv   = (const float*)d_in[8];
    const float* wq   = (const float*)d_in[9];
    const float* wk   = (const float*)d_in[10];
    const float* wipk = (const float*)d_in[11];
    float* out = (float*)d_out;

    k_round<<<DD * DD / 8 / 256, 256>>>(Wk, Wv);
    k_emb<<<(BB * TWOD) / 8, 256>>>(temb, Wada, bada);
    k_ipnorm<<<BB * LIP, 256>>>(ip);

    int gemm_smem = 2 * GNST * 128 * GST * sizeof(__half);   // 61440
    cudaFuncSetAttribute(k_gemm, cudaFuncAttributeMaxDynamicSharedMemorySize, gemm_smem);
    dim3 gg(DD / 128, (BB * LIP) / 128, 2);
    k_gemm<<<gg, 256, gemm_smem>>>();

    int totw = BB * HH * (LL * 3 + LIP * 2);
    k_scatter<<<totw / 8, 256>>>(q, k, v, wq, wk, wipk);

    int attn_smem = 2 * KB16;                                 // 69632
    cudaFuncSetAttribute(k_attn, cudaFuncAttributeMaxDynamicSharedMemorySize, attn_smem);
    dim3 ga(LL / 64, HH, BB);
    k_attn<<<ga, 128, attn_smem>>>(out);
}